// round 5
// baseline (speedup 1.0000x reference)
#include <cuda_runtime.h>
#include <cuda_bf16.h>
#include <math.h>
#include <stdint.h>

#define NTOK 4096
#define DIM  1024
#define HID  2048
#define NE   8

// ---------------------------------------------------------------------------
// Helpers
// ---------------------------------------------------------------------------
__device__ __forceinline__ uint32_t smem_to_u32(const void* p) {
    uint32_t a;
    asm("{ .reg .u64 t; cvta.to.shared.u64 t, %1; cvt.u32.u64 %0, t; }"
        : "=r"(a) : "l"(p));
    return a;
}

#define SWZ(rel) ((rel) ^ (((rel) >> 3) & 0x70))

#define CP_ASYNC(dst, src, sz) \
    asm volatile("cp.async.cg.shared.global [%0], [%1], 16, %2;" \
        :: "r"(dst), "l"(src), "r"(sz))
#define CP_COMMIT() asm volatile("cp.async.commit_group;")
#define CP_WAIT(N)  asm volatile("cp.async.wait_group %0;" :: "n"(N))

__device__ __forceinline__ void ldsm_x4(uint32_t addr, uint32_t* r) {
    asm volatile("ldmatrix.sync.aligned.m8n8.x4.shared.b16 {%0,%1,%2,%3}, [%4];"
        : "=r"(r[0]), "=r"(r[1]), "=r"(r[2]), "=r"(r[3]) : "r"(addr));
}
__device__ __forceinline__ void ldsm_x4_t(uint32_t addr, uint32_t* r) {
    asm volatile("ldmatrix.sync.aligned.m8n8.x4.trans.shared.b16 {%0,%1,%2,%3}, [%4];"
        : "=r"(r[0]), "=r"(r[1]), "=r"(r[2]), "=r"(r[3]) : "r"(addr));
}
__device__ __forceinline__ void mma_bf16(float* d, const uint32_t* a, const uint32_t* b) {
    asm volatile(
        "mma.sync.aligned.m16n8k16.row.col.f32.bf16.bf16.f32 "
        "{%0,%1,%2,%3}, {%4,%5,%6,%7}, {%8,%9}, {%0,%1,%2,%3};"
        : "+f"(d[0]), "+f"(d[1]), "+f"(d[2]), "+f"(d[3])
        : "r"(a[0]), "r"(a[1]), "r"(a[2]), "r"(a[3]), "r"(b[0]), "r"(b[1]));
}

__device__ __forceinline__ void cvt_hl(float f, __nv_bfloat16& h, __nv_bfloat16& l) {
    h = __float2bfloat16_rn(f);
    l = __float2bfloat16_rn(f - __bfloat162float(h));
}
__device__ __forceinline__ uint32_t pack2(__nv_bfloat16 a, __nv_bfloat16 b) {
    __nv_bfloat162 t = __halves2bfloat162(a, b);
    uint32_t r; memcpy(&r, &t, 4); return r;
}
__device__ __forceinline__ void cvt4(float4 f, uint2& hv, uint2& lv) {
    __nv_bfloat16 h0,l0,h1,l1,h2,l2,h3,l3;
    cvt_hl(f.x, h0, l0); cvt_hl(f.y, h1, l1);
    cvt_hl(f.z, h2, l2); cvt_hl(f.w, h3, l3);
    hv.x = pack2(h0, h1); hv.y = pack2(h2, h3);
    lv.x = pack2(l0, l1); lv.y = pack2(l2, l3);
}

// ---------------------------------------------------------------------------
// Scratch (device globals)
// ---------------------------------------------------------------------------
__device__ int   g_counts[NE];
__device__ int   g_off[NE + 1];
__device__ int   g_tok[NE * NTOK];
__device__ float g_wt[NE * NTOK];
__device__ __nv_bfloat16 g_xh[(size_t)NTOK * DIM];
__device__ __nv_bfloat16 g_xl[(size_t)NTOK * DIM];
__device__ __nv_bfloat16 g_w1h[(size_t)NE * DIM * HID];
__device__ __nv_bfloat16 g_w1l[(size_t)NE * DIM * HID];
__device__ __nv_bfloat16 g_w3h[(size_t)NE * DIM * HID];
__device__ __nv_bfloat16 g_w3l[(size_t)NE * DIM * HID];
__device__ __nv_bfloat16 g_w2h[(size_t)NE * HID * DIM];
__device__ __nv_bfloat16 g_w2l[(size_t)NE * HID * DIM];
__device__ __nv_bfloat16 g_hh[(size_t)(2 * NTOK) * HID];
__device__ __nv_bfloat16 g_hl[(size_t)(2 * NTOK) * HID];

// ---------------------------------------------------------------------------
// K0: zero output + counts
// ---------------------------------------------------------------------------
__global__ void zero_kernel(float* __restrict__ out, int n4) {
    int idx = blockIdx.x * blockDim.x + threadIdx.x;
    if (idx < NE) g_counts[idx] = 0;
    float4 z = make_float4(0.f, 0.f, 0.f, 0.f);
    float4* o4 = (float4*)out;
    for (int i = idx; i < n4; i += gridDim.x * blockDim.x) o4[i] = z;
}

// ---------------------------------------------------------------------------
// K-cvt: all three weights fp32 -> bf16 hi/lo planes, one launch, 16B stores
// ---------------------------------------------------------------------------
__global__ void cvtw_kernel(const float4* __restrict__ W1,
                            const float4* __restrict__ W3,
                            const float4* __restrict__ W2) {
    const int n8   = NE * DIM * HID / 8;   // 8-float chunks per tensor
    const int gper = gridDim.x / 3;
    int t  = blockIdx.x / gper;
    int bl = blockIdx.x % gper;
    const float4* s = (t == 0) ? W1 : ((t == 1) ? W3 : W2);
    __nv_bfloat16* dh = (t == 0) ? g_w1h : ((t == 1) ? g_w3h : g_w2h);
    __nv_bfloat16* dl = (t == 0) ? g_w1l : ((t == 1) ? g_w3l : g_w2l);
    for (int i = bl * blockDim.x + threadIdx.x; i < n8; i += gper * blockDim.x) {
        float4 a = s[2 * i], b = s[2 * i + 1];
        uint2 ha, la, hb, lb;
        cvt4(a, ha, la); cvt4(b, hb, lb);
        *(uint4*)(dh + (size_t)i * 8) = make_uint4(ha.x, ha.y, hb.x, hb.y);
        *(uint4*)(dl + (size_t)i * 8) = make_uint4(la.x, la.y, lb.x, lb.y);
    }
}

// ---------------------------------------------------------------------------
// K1: routing + x hi/lo conversion fused (one warp/token)
// ---------------------------------------------------------------------------
__global__ void route_kernel(const float4* __restrict__ x4,
                             const float* __restrict__ Wg) {
    int warp = (blockIdx.x * blockDim.x + threadIdx.x) >> 5;
    int lane = threadIdx.x & 31;
    if (warp >= NTOK) return;

    float sc[NE];
#pragma unroll
    for (int e = 0; e < NE; e++) sc[e] = 0.f;

#pragma unroll
    for (int j = 0; j < 8; j++) {
        int i4 = j * 32 + lane;               // 0..255 float4 per row
        float4 xv = x4[(size_t)warp * (DIM / 4) + i4];
        uint2 hv, lv; cvt4(xv, hv, lv);
        *(uint2*)(g_xh + (size_t)warp * DIM + i4 * 4) = hv;
        *(uint2*)(g_xl + (size_t)warp * DIM + i4 * 4) = lv;
        float xs[4] = {xv.x, xv.y, xv.z, xv.w};
#pragma unroll
        for (int c = 0; c < 4; c++) {
            int row = i4 * 4 + c;
#pragma unroll
            for (int e = 0; e < NE; e++)
                sc[e] += xs[c] * Wg[row * NE + e];
        }
    }
#pragma unroll
    for (int o = 16; o > 0; o >>= 1)
#pragma unroll
        for (int e = 0; e < NE; e++)
            sc[e] += __shfl_xor_sync(0xffffffffu, sc[e], o);

    if (lane == 0) {
        int i0 = 0; float s0 = sc[0];
#pragma unroll
        for (int e = 1; e < NE; e++) if (sc[e] > s0) { s0 = sc[e]; i0 = e; }
        int i1 = -1; float s1 = -INFINITY;
#pragma unroll
        for (int e = 0; e < NE; e++)
            if (e != i0 && sc[e] > s1) { s1 = sc[e]; i1 = e; }
        float e1  = expf(s1 - s0);
        float inv = 1.f / (1.f + e1);
        int p0 = atomicAdd(&g_counts[i0], 1);
        g_tok[i0 * NTOK + p0] = warp;
        g_wt [i0 * NTOK + p0] = inv;
        int p1 = atomicAdd(&g_counts[i1], 1);
        g_tok[i1 * NTOK + p1] = warp;
        g_wt [i1 * NTOK + p1] = e1 * inv;
    }
}

__global__ void scan_kernel() {
    int acc = 0;
#pragma unroll
    for (int e = 0; e < NE; e++) { g_off[e] = acc; acc += g_counts[e]; }
    g_off[NE] = acc;
}

// ---------------------------------------------------------------------------
// K3: FFN1 — BM=128, BN=128, BK=32, 512 thr, 3-stage cp.async, 1 barrier/iter.
// Stage: A 16KB + B 32KB = 48KB; x3 = 144KB dynamic.
// ---------------------------------------------------------------------------
#define F1_STAGE 49152
#define F2_STAGE 32768

__global__ __launch_bounds__(512, 1) void ffn1_kernel() {
    extern __shared__ char sm[];
    __shared__ int s_tok[128];

    int e   = blockIdx.z;
    int cnt = g_counts[e];
    int m0  = blockIdx.y * 128;
    if (m0 >= cnt) return;
    int n0   = blockIdx.x * 128;
    int base = g_off[e];

    int tid = threadIdx.x, wid = tid >> 5, l = tid & 31;
    int mw = (wid >> 2) * 32, nw = (wid & 3) * 32;
    int half = nw >> 6, nwl = nw & 63;

    if (tid < 128) {
        int mg = m0 + tid;
        s_tok[tid] = (mg < cnt) ? g_tok[e * NTOK + mg] : -1;
    }
    __syncthreads();

    uint32_t sbase = smem_to_u32(sm);
    size_t eoffW = (size_t)e * DIM * HID;

    auto load_tile = [&](int it, int b) {
        int kb = it * 32;
        uint32_t abase = sbase + b * F1_STAGE;
        uint32_t bbase = abase + 16384;
#pragma unroll
        for (int j = 0; j < 2; j++) {
            int c = tid + j * 512;
            int row = c >> 3, sub = c & 7;
            int pl = sub >> 2, cc = sub & 3;
            int tok = s_tok[row];
            const __nv_bfloat16* sp = pl ? g_xl : g_xh;
            const void* src = sp + ((size_t)(tok < 0 ? 0 : tok) * DIM + kb + cc * 8);
            uint32_t dst = abase + SWZ((uint32_t)(row * 128 + pl * 64 + cc * 16));
            int sz = (tok < 0) ? 0 : 16;
            CP_ASYNC(dst, src, sz);
        }
#pragma unroll
        for (int j = 0; j < 4; j++) {
            int c = tid + j * 512;
            int p = c >> 9, w = c & 511;
            int kr = w >> 4, n = (w & 15) * 8;
            const __nv_bfloat16* sp;
            if      (p == 0) sp = g_w1h;
            else if (p == 1) sp = g_w1l;
            else if (p == 2) sp = g_w3h;
            else             sp = g_w3l;
            const void* src = sp + (eoffW + (size_t)(kb + kr) * HID + n0 + n);
            uint32_t dst = bbase + p * 8192 + (n >> 6) * 4096
                         + SWZ((uint32_t)(kr * 128 + (n & 63) * 2));
            CP_ASYNC(dst, src, 16);
        }
    };

    float acc1[2][4][4] = {};
    float acc3[2][4][4] = {};

    const int NIT = DIM / 32;
    load_tile(0, 0); CP_COMMIT();
    load_tile(1, 1); CP_COMMIT();

    for (int it = 0; it < NIT; it++) {
        CP_WAIT(1);
        __syncthreads();
        if (it + 2 < NIT) load_tile(it + 2, (it + 2) % 3);
        CP_COMMIT();                     // always commit (possibly empty group)

        uint32_t aB = sbase + (it % 3) * F1_STAGE;
        uint32_t bB = aB + 16384;
        uint32_t b1h = bB + 0 * 8192 + half * 4096;
        uint32_t b1l = bB + 1 * 8192 + half * 4096;
        uint32_t b3h = bB + 2 * 8192 + half * 4096;
        uint32_t b3l = bB + 3 * 8192 + half * 4096;

#pragma unroll
        for (int ks = 0; ks < 2; ks++) {
            uint32_t ah[2][4], al[2][4];
#pragma unroll
            for (int mt = 0; mt < 2; mt++) {
                int row  = mw + mt * 16 + ((l >> 3) & 1) * 8 + (l & 7);
                int kbyt = (ks * 16 + (l >> 4) * 8) * 2;
                ldsm_x4(aB + SWZ((uint32_t)(row * 128 + kbyt)), ah[mt]);
                ldsm_x4(aB + SWZ((uint32_t)(row * 128 + 64 + kbyt)), al[mt]);
            }
            int krow = ks * 16 + ((l >> 3) & 1) * 8 + (l & 7);
            uint32_t rb0 = krow * 128 + (nwl + (l >> 4) * 8) * 2;
            uint32_t rb1 = rb0 + 32;
            uint32_t s0 = SWZ(rb0), s1 = SWZ(rb1);

            {   // W1
                uint32_t bh[8], bl[8];
                ldsm_x4_t(b1h + s0, bh); ldsm_x4_t(b1h + s1, bh + 4);
                ldsm_x4_t(b1l + s0, bl); ldsm_x4_t(b1l + s1, bl + 4);
#pragma unroll
                for (int mt = 0; mt < 2; mt++)
#pragma unroll
                    for (int nj = 0; nj < 4; nj++) {
                        mma_bf16(acc1[mt][nj], ah[mt], &bh[nj * 2]);
                        mma_bf16(acc1[mt][nj], ah[mt], &bl[nj * 2]);
                        mma_bf16(acc1[mt][nj], al[mt], &bh[nj * 2]);
                    }
            }
            {   // W3
                uint32_t bh[8], bl[8];
                ldsm_x4_t(b3h + s0, bh); ldsm_x4_t(b3h + s1, bh + 4);
                ldsm_x4_t(b3l + s0, bl); ldsm_x4_t(b3l + s1, bl + 4);
#pragma unroll
                for (int mt = 0; mt < 2; mt++)
#pragma unroll
                    for (int nj = 0; nj < 4; nj++) {
                        mma_bf16(acc3[mt][nj], ah[mt], &bh[nj * 2]);
                        mma_bf16(acc3[mt][nj], ah[mt], &bl[nj * 2]);
                        mma_bf16(acc3[mt][nj], al[mt], &bh[nj * 2]);
                    }
            }
        }
        // No trailing barrier: the 3-buffer rotation + leading barrier
        // guarantee the buffer loaded next iter was consumed last iter.
    }

    // ---- epilogue: SwiGLU -> g_hh/g_hl ----
#pragma unroll
    for (int mt = 0; mt < 2; mt++) {
#pragma unroll
        for (int hf = 0; hf < 2; hf++) {
            int row = m0 + mw + mt * 16 + (l >> 2) + hf * 8;
            if (row < cnt) {
                size_t rb = (size_t)(base + row) * HID + n0 + nw;
#pragma unroll
                for (int nj = 0; nj < 4; nj++) {
                    float a0 = acc1[mt][nj][hf * 2 + 0];
                    float a1 = acc1[mt][nj][hf * 2 + 1];
                    float h0 = a0 / (1.f + __expf(-a0)) * acc3[mt][nj][hf * 2 + 0];
                    float h1 = a1 / (1.f + __expf(-a1)) * acc3[mt][nj][hf * 2 + 1];
                    int c = nj * 8 + (l & 3) * 2;
                    __nv_bfloat16 h0h, h0l, h1h, h1l;
                    cvt_hl(h0, h0h, h0l); cvt_hl(h1, h1h, h1l);
                    *(uint32_t*)(g_hh + rb + c) = pack2(h0h, h1h);
                    *(uint32_t*)(g_hl + rb + c) = pack2(h0l, h1l);
                }
            }
        }
    }
}

// ---------------------------------------------------------------------------
// K4: FFN2 — BM=128, BN=128, BK=32, 512 thr, 3-stage cp.async.
// Stage: A 16KB + B 16KB = 32KB; x3 = 96KB dynamic.
// ---------------------------------------------------------------------------
__global__ __launch_bounds__(512, 1) void ffn2_kernel(float* __restrict__ out) {
    extern __shared__ char sm[];

    int e   = blockIdx.z;
    int cnt = g_counts[e];
    int m0  = blockIdx.y * 128;
    if (m0 >= cnt) return;
    int n0   = blockIdx.x * 128;
    int base = g_off[e];

    int tid = threadIdx.x, wid = tid >> 5, l = tid & 31;
    int mw = (wid >> 2) * 32, nw = (wid & 3) * 32;
    int half = nw >> 6, nwl = nw & 63;

    uint32_t sbase = smem_to_u32(sm);
    size_t eoffW = (size_t)e * HID * DIM;

    auto load_tile = [&](int it, int b) {
        int kb = it * 32;
        uint32_t abase = sbase + b * F2_STAGE;
        uint32_t bbase = abase + 16384;
#pragma unroll
        for (int j = 0; j < 2; j++) {
            int c = tid + j * 512;
            int row = c >> 3, sub = c & 7;
            int pl = sub >> 2, cc = sub & 3;
            int mg = m0 + row;
            bool v = mg < cnt;
            const __nv_bfloat16* sp = pl ? g_hl : g_hh;
            const void* src = sp + ((size_t)(v ? base + mg : 0) * HID + kb + cc * 8);
            uint32_t dst = abase + SWZ((uint32_t)(row * 128 + pl * 64 + cc * 16));
            int sz = v ? 16 : 0;
            CP_ASYNC(dst, src, sz);
        }
#pragma unroll
        for (int j = 0; j < 2; j++) {
            int c = tid + j * 512;
            int p = c >> 9, w = c & 511;
            int kr = w >> 4, n = (w & 15) * 8;
            const __nv_bfloat16* sp = p ? g_w2l : g_w2h;
            const void* src = sp + (eoffW + (size_t)(kb + kr) * DIM + n0 + n);
            uint32_t dst = bbase + p * 8192 + (n >> 6) * 4096
                         + SWZ((uint32_t)(kr * 128 + (n & 63) * 2));
            CP_ASYNC(dst, src, 16);
        }
    };

    float acc[2][4][4] = {};

    const int NIT = HID / 32;
    load_tile(0, 0); CP_COMMIT();
    load_tile(1, 1); CP_COMMIT();

    for (int it = 0; it < NIT; it++) {
        CP_WAIT(1);
        __syncthreads();
        if (it + 2 < NIT) load_tile(it + 2, (it + 2) % 3);
        CP_COMMIT();

        uint32_t aB = sbase + (it % 3) * F2_STAGE;
        uint32_t bB = aB + 16384;
        uint32_t bH = bB + 0 * 8192 + half * 4096;
        uint32_t bL = bB + 1 * 8192 + half * 4096;

#pragma unroll
        for (int ks = 0; ks < 2; ks++) {
            uint32_t ah[2][4], al[2][4];
#pragma unroll
            for (int mt = 0; mt < 2; mt++) {
                int row  = mw + mt * 16 + ((l >> 3) & 1) * 8 + (l & 7);
                int kbyt = (ks * 16 + (l >> 4) * 8) * 2;
                ldsm_x4(aB + SWZ((uint32_t)(row * 128 + kbyt)), ah[mt]);
                ldsm_x4(aB + SWZ((uint32_t)(row * 128 + 64 + kbyt)), al[mt]);
            }
            int krow = ks * 16 + ((l >> 3) & 1) * 8 + (l & 7);
            uint32_t rb0 = krow * 128 + (nwl + (l >> 4) * 8) * 2;
            uint32_t rb1 = rb0 + 32;
            uint32_t s0 = SWZ(rb0), s1 = SWZ(rb1);

            uint32_t bh[8], bl[8];
            ldsm_x4_t(bH + s0, bh); ldsm_x4_t(bH + s1, bh + 4);
            ldsm_x4_t(bL + s0, bl); ldsm_x4_t(bL + s1, bl + 4);
#pragma unroll
            for (int mt = 0; mt < 2; mt++)
#pragma unroll
                for (int nj = 0; nj < 4; nj++) {
                    mma_bf16(acc[mt][nj], ah[mt], &bh[nj * 2]);
                    mma_bf16(acc[mt][nj], ah[mt], &bl[nj * 2]);
                    mma_bf16(acc[mt][nj], al[mt], &bh[nj * 2]);
                }
        }
    }

    // ---- epilogue: out[tok] += w * acc ----
#pragma unroll
    for (int mt = 0; mt < 2; mt++) {
#pragma unroll
        for (int hf = 0; hf < 2; hf++) {
            int row = m0 + mw + mt * 16 + (l >> 2) + hf * 8;
            if (row < cnt) {
                int   tok = g_tok[e * NTOK + row];
                float w   = g_wt [e * NTOK + row];
                float* orow = out + (size_t)tok * DIM + n0 + nw;
#pragma unroll
                for (int nj = 0; nj < 4; nj++) {
                    int c = nj * 8 + (l & 3) * 2;
                    atomicAdd(&orow[c],     w * acc[mt][nj][hf * 2 + 0]);
                    atomicAdd(&orow[c + 1], w * acc[mt][nj][hf * 2 + 1]);
                }
            }
        }
    }
}

// ---------------------------------------------------------------------------
// Launch
// ---------------------------------------------------------------------------
extern "C" void kernel_launch(void* const* d_in, const int* in_sizes, int n_in,
                              void* d_out, int out_size) {
    const float* x  = (const float*)d_in[0];
    const float* Wg = (const float*)d_in[1];
    const float* W1 = (const float*)d_in[2];
    const float* W3 = (const float*)d_in[3];
    const float* W2 = (const float*)d_in[4];
    float* out = (float*)d_out;

    cudaFuncSetAttribute(ffn1_kernel,
        cudaFuncAttributeMaxDynamicSharedMemorySize, 3 * F1_STAGE);
    cudaFuncSetAttribute(ffn2_kernel,
        cudaFuncAttributeMaxDynamicSharedMemorySize, 3 * F2_STAGE);

    zero_kernel<<<1024, 256>>>(out, out_size / 4);
    cvtw_kernel<<<3 * 2048, 256>>>((const float4*)W1, (const float4*)W3,
                                   (const float4*)W2);
    route_kernel<<<NTOK / 8, 256>>>((const float4*)x, Wg);
    scan_kernel<<<1, 1>>>();

    dim3 g1(HID / 128, NTOK / 128, NE);   // 16 x 32 x 8
    ffn1_kernel<<<g1, 512, 3 * F1_STAGE>>>();

    dim3 g2(DIM / 128, NTOK / 128, NE);   // 8 x 32 x 8
    ffn2_kernel<<<g2, 512, 3 * F2_STAGE>>>(out);
}

// round 7
// speedup vs baseline: 1.1008x; 1.1008x over previous
#include <cuda_runtime.h>
#include <cuda_bf16.h>
#include <math.h>
#include <stdint.h>

#define NTOK 4096
#define DIM  1024
#define HID  2048
#define NE   8

// ---------------------------------------------------------------------------
// Helpers
// ---------------------------------------------------------------------------
__device__ __forceinline__ uint32_t smem_to_u32(const void* p) {
    uint32_t a;
    asm("{ .reg .u64 t; cvta.to.shared.u64 t, %1; cvt.u32.u64 %0, t; }"
        : "=r"(a) : "l"(p));
    return a;
}

#define SWZ(rel) ((rel) ^ (((rel) >> 3) & 0x70))

#define CP_ASYNC(dst, src, sz) \
    asm volatile("cp.async.cg.shared.global [%0], [%1], 16, %2;" \
        :: "r"(dst), "l"(src), "r"(sz))
#define CP_COMMIT() asm volatile("cp.async.commit_group;")
#define CP_WAIT(N)  asm volatile("cp.async.wait_group %0;" :: "n"(N))

__device__ __forceinline__ void ldsm_x4(uint32_t addr, uint32_t* r) {
    asm volatile("ldmatrix.sync.aligned.m8n8.x4.shared.b16 {%0,%1,%2,%3}, [%4];"
        : "=r"(r[0]), "=r"(r[1]), "=r"(r[2]), "=r"(r[3]) : "r"(addr));
}
__device__ __forceinline__ void ldsm_x4_t(uint32_t addr, uint32_t* r) {
    asm volatile("ldmatrix.sync.aligned.m8n8.x4.trans.shared.b16 {%0,%1,%2,%3}, [%4];"
        : "=r"(r[0]), "=r"(r[1]), "=r"(r[2]), "=r"(r[3]) : "r"(addr));
}
__device__ __forceinline__ void mma_bf16(float* d, const uint32_t* a, const uint32_t* b) {
    asm volatile(
        "mma.sync.aligned.m16n8k16.row.col.f32.bf16.bf16.f32 "
        "{%0,%1,%2,%3}, {%4,%5,%6,%7}, {%8,%9}, {%0,%1,%2,%3};"
        : "+f"(d[0]), "+f"(d[1]), "+f"(d[2]), "+f"(d[3])
        : "r"(a[0]), "r"(a[1]), "r"(a[2]), "r"(a[3]), "r"(b[0]), "r"(b[1]));
}

__device__ __forceinline__ void cvt_hl(float f, __nv_bfloat16& h, __nv_bfloat16& l) {
    h = __float2bfloat16_rn(f);
    l = __float2bfloat16_rn(f - __bfloat162float(h));
}
__device__ __forceinline__ uint32_t pack2(__nv_bfloat16 a, __nv_bfloat16 b) {
    __nv_bfloat162 t = __halves2bfloat162(a, b);
    uint32_t r; memcpy(&r, &t, 4); return r;
}
__device__ __forceinline__ void cvt4(float4 f, uint2& hv, uint2& lv) {
    __nv_bfloat16 h0,l0,h1,l1,h2,l2,h3,l3;
    cvt_hl(f.x, h0, l0); cvt_hl(f.y, h1, l1);
    cvt_hl(f.z, h2, l2); cvt_hl(f.w, h3, l3);
    hv.x = pack2(h0, h1); hv.y = pack2(h2, h3);
    lv.x = pack2(l0, l1); lv.y = pack2(l2, l3);
}

// ---------------------------------------------------------------------------
// Scratch (device globals)
// ---------------------------------------------------------------------------
__device__ int   g_counts[NE];
__device__ int   g_tok[NE * NTOK];
__device__ float g_wt[NE * NTOK];
__device__ __nv_bfloat16 g_xh[(size_t)NTOK * DIM];
__device__ __nv_bfloat16 g_xl[(size_t)NTOK * DIM];
__device__ __nv_bfloat16 g_w1h[(size_t)NE * DIM * HID];
__device__ __nv_bfloat16 g_w1l[(size_t)NE * DIM * HID];
__device__ __nv_bfloat16 g_w3h[(size_t)NE * DIM * HID];
__device__ __nv_bfloat16 g_w3l[(size_t)NE * DIM * HID];
__device__ __nv_bfloat16 g_w2h[(size_t)NE * HID * DIM];
__device__ __nv_bfloat16 g_w2l[(size_t)NE * HID * DIM];
__device__ __nv_bfloat16 g_hh[(size_t)(2 * NTOK) * HID];
__device__ __nv_bfloat16 g_hl[(size_t)(2 * NTOK) * HID];

// ---------------------------------------------------------------------------
// K0: zero output + counts
// ---------------------------------------------------------------------------
__global__ void zero_kernel(float* __restrict__ out, int n4) {
    int idx = blockIdx.x * blockDim.x + threadIdx.x;
    if (idx < NE) g_counts[idx] = 0;
    float4 z = make_float4(0.f, 0.f, 0.f, 0.f);
    float4* o4 = (float4*)out;
    for (int i = idx; i < n4; i += gridDim.x * blockDim.x) o4[i] = z;
}

// ---------------------------------------------------------------------------
// K-cvt: all three weights fp32 -> bf16 hi/lo planes, one launch, 16B stores
// ---------------------------------------------------------------------------
__global__ void cvtw_kernel(const float4* __restrict__ W1,
                            const float4* __restrict__ W3,
                            const float4* __restrict__ W2) {
    const int n8   = NE * DIM * HID / 8;
    const int gper = gridDim.x / 3;
    int t  = blockIdx.x / gper;
    int bl = blockIdx.x % gper;
    const float4* s = (t == 0) ? W1 : ((t == 1) ? W3 : W2);
    __nv_bfloat16* dh = (t == 0) ? g_w1h : ((t == 1) ? g_w3h : g_w2h);
    __nv_bfloat16* dl = (t == 0) ? g_w1l : ((t == 1) ? g_w3l : g_w2l);
    for (int i = bl * blockDim.x + threadIdx.x; i < n8; i += gper * blockDim.x) {
        float4 a = s[2 * i], b = s[2 * i + 1];
        uint2 ha, la, hb, lb;
        cvt4(a, ha, la); cvt4(b, hb, lb);
        *(uint4*)(dh + (size_t)i * 8) = make_uint4(ha.x, ha.y, hb.x, hb.y);
        *(uint4*)(dl + (size_t)i * 8) = make_uint4(la.x, la.y, lb.x, lb.y);
    }
}

// ---------------------------------------------------------------------------
// K1: routing + x hi/lo conversion fused (one warp/token)
// ---------------------------------------------------------------------------
__global__ void route_kernel(const float4* __restrict__ x4,
                             const float* __restrict__ Wg) {
    int warp = (blockIdx.x * blockDim.x + threadIdx.x) >> 5;
    int lane = threadIdx.x & 31;
    if (warp >= NTOK) return;

    float sc[NE];
#pragma unroll
    for (int e = 0; e < NE; e++) sc[e] = 0.f;

#pragma unroll
    for (int j = 0; j < 8; j++) {
        int i4 = j * 32 + lane;
        float4 xv = x4[(size_t)warp * (DIM / 4) + i4];
        uint2 hv, lv; cvt4(xv, hv, lv);
        *(uint2*)(g_xh + (size_t)warp * DIM + i4 * 4) = hv;
        *(uint2*)(g_xl + (size_t)warp * DIM + i4 * 4) = lv;
        float xs[4] = {xv.x, xv.y, xv.z, xv.w};
#pragma unroll
        for (int c = 0; c < 4; c++) {
            int row = i4 * 4 + c;
#pragma unroll
            for (int e = 0; e < NE; e++)
                sc[e] += xs[c] * Wg[row * NE + e];
        }
    }
#pragma unroll
    for (int o = 16; o > 0; o >>= 1)
#pragma unroll
        for (int e = 0; e < NE; e++)
            sc[e] += __shfl_xor_sync(0xffffffffu, sc[e], o);

    if (lane == 0) {
        int i0 = 0; float s0 = sc[0];
#pragma unroll
        for (int e = 1; e < NE; e++) if (sc[e] > s0) { s0 = sc[e]; i0 = e; }
        int i1 = -1; float s1 = -INFINITY;
#pragma unroll
        for (int e = 0; e < NE; e++)
            if (e != i0 && sc[e] > s1) { s1 = sc[e]; i1 = e; }
        float e1  = expf(s1 - s0);
        float inv = 1.f / (1.f + e1);
        int p0 = atomicAdd(&g_counts[i0], 1);
        g_tok[i0 * NTOK + p0] = warp;
        g_wt [i0 * NTOK + p0] = inv;
        int p1 = atomicAdd(&g_counts[i1], 1);
        g_tok[i1 * NTOK + p1] = warp;
        g_wt [i1 * NTOK + p1] = e1 * inv;
    }
}

__device__ __forceinline__ int expert_base(int e) {
    int b = 0;
#pragma unroll
    for (int j = 0; j < NE; j++) if (j < e) b += g_counts[j];
    return b;
}

// ---------------------------------------------------------------------------
// K3: FFN1 — BM=128, BN=64, BK=32, 256 thr, 2 CTAs/SM, 3-stage pipeline.
// Loop body: wait(1) -> barrier -> mma(it) -> load(it+2) -> commit.
// Stage: A 16KB + B 16KB = 32KB; x3 = 96KB dynamic.
// ---------------------------------------------------------------------------
#define F1_STAGE 32768
#define F2_STAGE 24576

__global__ __launch_bounds__(256, 2) void ffn1_kernel() {
    extern __shared__ char sm[];
    __shared__ int s_tok[128];

    int e   = blockIdx.z;
    int cnt = g_counts[e];
    int m0  = blockIdx.y * 128;
    if (m0 >= cnt) return;
    int n0   = blockIdx.x * 64;
    int base = expert_base(e);

    int tid = threadIdx.x, wid = tid >> 5, l = tid & 31;
    int mw = (wid >> 1) * 32, nw = (wid & 1) * 32;

    if (tid < 128) {
        int mg = m0 + tid;
        s_tok[tid] = (mg < cnt) ? g_tok[e * NTOK + mg] : -1;
    }
    __syncthreads();

    uint32_t sbase = smem_to_u32(sm);
    size_t eoffW = (size_t)e * DIM * HID;

    auto load_tile = [&](int it, int b) {
        int kb = it * 32;
        uint32_t abase = sbase + b * F1_STAGE;
        uint32_t bbase = abase + 16384;
        // A: 1024 16B chunks (128 rows x 8: 4 hi + 4 lo)
#pragma unroll
        for (int j = 0; j < 4; j++) {
            int c = tid + j * 256;
            int row = c >> 3, sub = c & 7;
            int pl = sub >> 2, cc = sub & 3;
            int tok = s_tok[row];
            const __nv_bfloat16* sp = pl ? g_xl : g_xh;
            const void* src = sp + ((size_t)(tok < 0 ? 0 : tok) * DIM + kb + cc * 8);
            uint32_t dst = abase + SWZ((uint32_t)(row * 128 + pl * 64 + cc * 16));
            int sz = (tok < 0) ? 0 : 16;
            CP_ASYNC(dst, src, sz);
        }
        // B: 1024 chunks over 4 planes (W1h,W1l,W3h,W3l), 32k x 64n each
#pragma unroll
        for (int j = 0; j < 4; j++) {
            int c = tid + j * 256;
            int p = c >> 8, w = c & 255;
            int kr = w >> 3, n = (w & 7) * 8;
            const __nv_bfloat16* sp;
            if      (p == 0) sp = g_w1h;
            else if (p == 1) sp = g_w1l;
            else if (p == 2) sp = g_w3h;
            else             sp = g_w3l;
            const void* src = sp + (eoffW + (size_t)(kb + kr) * HID + n0 + n);
            uint32_t dst = bbase + p * 4096 + SWZ((uint32_t)(kr * 128 + n * 2));
            CP_ASYNC(dst, src, 16);
        }
    };

    float acc1[2][4][4] = {};
    float acc3[2][4][4] = {};

    const int NIT = DIM / 32;
    load_tile(0, 0); CP_COMMIT();
    load_tile(1, 1); CP_COMMIT();

    for (int it = 0; it < NIT; it++) {
        CP_WAIT(1);
        __syncthreads();   // all threads' stage-it groups complete; prev readers done

        uint32_t aB = sbase + (it % 3) * F1_STAGE;
        uint32_t bB = aB + 16384;
        uint32_t b1h = bB + 0 * 4096, b1l = bB + 1 * 4096;
        uint32_t b3h = bB + 2 * 4096, b3l = bB + 3 * 4096;

#pragma unroll
        for (int ks = 0; ks < 2; ks++) {
            uint32_t ah[2][4], al[2][4];
#pragma unroll
            for (int mt = 0; mt < 2; mt++) {
                int row  = mw + mt * 16 + ((l >> 3) & 1) * 8 + (l & 7);
                int kbyt = (ks * 16 + (l >> 4) * 8) * 2;
                ldsm_x4(aB + SWZ((uint32_t)(row * 128 + kbyt)), ah[mt]);
                ldsm_x4(aB + SWZ((uint32_t)(row * 128 + 64 + kbyt)), al[mt]);
            }
            int krow = ks * 16 + ((l >> 3) & 1) * 8 + (l & 7);
            uint32_t rb0 = krow * 128 + (nw + (l >> 4) * 8) * 2;
            uint32_t rb1 = rb0 + 32;
            uint32_t s0 = SWZ(rb0), s1 = SWZ(rb1);

            {   // W1
                uint32_t bh[8], bl[8];
                ldsm_x4_t(b1h + s0, bh); ldsm_x4_t(b1h + s1, bh + 4);
                ldsm_x4_t(b1l + s0, bl); ldsm_x4_t(b1l + s1, bl + 4);
#pragma unroll
                for (int mt = 0; mt < 2; mt++)
#pragma unroll
                    for (int nj = 0; nj < 4; nj++) {
                        mma_bf16(acc1[mt][nj], ah[mt], &bh[nj * 2]);
                        mma_bf16(acc1[mt][nj], ah[mt], &bl[nj * 2]);
                        mma_bf16(acc1[mt][nj], al[mt], &bh[nj * 2]);
                    }
            }
            {   // W3
                uint32_t bh[8], bl[8];
                ldsm_x4_t(b3h + s0, bh); ldsm_x4_t(b3h + s1, bh + 4);
                ldsm_x4_t(b3l + s0, bl); ldsm_x4_t(b3l + s1, bl + 4);
#pragma unroll
                for (int mt = 0; mt < 2; mt++)
#pragma unroll
                    for (int nj = 0; nj < 4; nj++) {
                        mma_bf16(acc3[mt][nj], ah[mt], &bh[nj * 2]);
                        mma_bf16(acc3[mt][nj], ah[mt], &bl[nj * 2]);
                        mma_bf16(acc3[mt][nj], al[mt], &bh[nj * 2]);
                    }
            }
        }

        // Prefetch stage it+2. Buffer (it+2)%3 == (it-1)%3: its readers all
        // passed the barrier at the top of THIS iteration -> safe.
        if (it + 2 < NIT) load_tile(it + 2, (it + 2) % 3);
        CP_COMMIT();
    }

    // ---- epilogue: SwiGLU -> g_hh/g_hl ----
#pragma unroll
    for (int mt = 0; mt < 2; mt++) {
#pragma unroll
        for (int hf = 0; hf < 2; hf++) {
            int row = m0 + mw + mt * 16 + (l >> 2) + hf * 8;
            if (row < cnt) {
                size_t rb = (size_t)(base + row) * HID + n0 + nw;
#pragma unroll
                for (int nj = 0; nj < 4; nj++) {
                    float a0 = acc1[mt][nj][hf * 2 + 0];
                    float a1 = acc1[mt][nj][hf * 2 + 1];
                    float h0 = a0 / (1.f + __expf(-a0)) * acc3[mt][nj][hf * 2 + 0];
                    float h1 = a1 / (1.f + __expf(-a1)) * acc3[mt][nj][hf * 2 + 1];
                    int c = nj * 8 + (l & 3) * 2;
                    __nv_bfloat16 h0h, h0l, h1h, h1l;
                    cvt_hl(h0, h0h, h0l); cvt_hl(h1, h1h, h1l);
                    *(uint32_t*)(g_hh + rb + c) = pack2(h0h, h1h);
                    *(uint32_t*)(g_hl + rb + c) = pack2(h0l, h1l);
                }
            }
        }
    }
}

// ---------------------------------------------------------------------------
// K4: FFN2 — BM=128, BN=64, BK=32, 256 thr, 2 CTAs/SM, 3-stage pipeline.
// Stage: A 16KB + B 8KB = 24KB; x3 = 72KB dynamic.
// ---------------------------------------------------------------------------
__global__ __launch_bounds__(256, 2) void ffn2_kernel(float* __restrict__ out) {
    extern __shared__ char sm[];

    int e   = blockIdx.z;
    int cnt = g_counts[e];
    int m0  = blockIdx.y * 128;
    if (m0 >= cnt) return;
    int n0   = blockIdx.x * 64;
    int base = expert_base(e);

    int tid = threadIdx.x, wid = tid >> 5, l = tid & 31;
    int mw = (wid >> 1) * 32, nw = (wid & 1) * 32;

    uint32_t sbase = smem_to_u32(sm);
    size_t eoffW = (size_t)e * HID * DIM;

    auto load_tile = [&](int it, int b) {
        int kb = it * 32;
        uint32_t abase = sbase + b * F2_STAGE;
        uint32_t bbase = abase + 16384;
#pragma unroll
        for (int j = 0; j < 4; j++) {
            int c = tid + j * 256;
            int row = c >> 3, sub = c & 7;
            int pl = sub >> 2, cc = sub & 3;
            int mg = m0 + row;
            bool v = mg < cnt;
            const __nv_bfloat16* sp = pl ? g_hl : g_hh;
            const void* src = sp + ((size_t)(v ? base + mg : 0) * HID + kb + cc * 8);
            uint32_t dst = abase + SWZ((uint32_t)(row * 128 + pl * 64 + cc * 16));
            int sz = v ? 16 : 0;
            CP_ASYNC(dst, src, sz);
        }
#pragma unroll
        for (int j = 0; j < 2; j++) {
            int c = tid + j * 256;
            int p = c >> 8, w = c & 255;
            int kr = w >> 3, n = (w & 7) * 8;
            const __nv_bfloat16* sp = p ? g_w2l : g_w2h;
            const void* src = sp + (eoffW + (size_t)(kb + kr) * DIM + n0 + n);
            uint32_t dst = bbase + p * 4096 + SWZ((uint32_t)(kr * 128 + n * 2));
            CP_ASYNC(dst, src, 16);
        }
    };

    float acc[2][4][4] = {};

    const int NIT = HID / 32;
    load_tile(0, 0); CP_COMMIT();
    load_tile(1, 1); CP_COMMIT();

    for (int it = 0; it < NIT; it++) {
        CP_WAIT(1);
        __syncthreads();

        uint32_t aB = sbase + (it % 3) * F2_STAGE;
        uint32_t bB = aB + 16384;
        uint32_t bH = bB, bL = bB + 4096;

#pragma unroll
        for (int ks = 0; ks < 2; ks++) {
            uint32_t ah[2][4], al[2][4];
#pragma unroll
            for (int mt = 0; mt < 2; mt++) {
                int row  = mw + mt * 16 + ((l >> 3) & 1) * 8 + (l & 7);
                int kbyt = (ks * 16 + (l >> 4) * 8) * 2;
                ldsm_x4(aB + SWZ((uint32_t)(row * 128 + kbyt)), ah[mt]);
                ldsm_x4(aB + SWZ((uint32_t)(row * 128 + 64 + kbyt)), al[mt]);
            }
            int krow = ks * 16 + ((l >> 3) & 1) * 8 + (l & 7);
            uint32_t rb0 = krow * 128 + (nw + (l >> 4) * 8) * 2;
            uint32_t rb1 = rb0 + 32;
            uint32_t s0 = SWZ(rb0), s1 = SWZ(rb1);

            uint32_t bh[8], bl[8];
            ldsm_x4_t(bH + s0, bh); ldsm_x4_t(bH + s1, bh + 4);
            ldsm_x4_t(bL + s0, bl); ldsm_x4_t(bL + s1, bl + 4);
#pragma unroll
            for (int mt = 0; mt < 2; mt++)
#pragma unroll
                for (int nj = 0; nj < 4; nj++) {
                    mma_bf16(acc[mt][nj], ah[mt], &bh[nj * 2]);
                    mma_bf16(acc[mt][nj], ah[mt], &bl[nj * 2]);
                    mma_bf16(acc[mt][nj], al[mt], &bh[nj * 2]);
                }
        }

        if (it + 2 < NIT) load_tile(it + 2, (it + 2) % 3);
        CP_COMMIT();
    }

    // ---- epilogue: out[tok] += w * acc ----
#pragma unroll
    for (int mt = 0; mt < 2; mt++) {
#pragma unroll
        for (int hf = 0; hf < 2; hf++) {
            int row = m0 + mw + mt * 16 + (l >> 2) + hf * 8;
            if (row < cnt) {
                int   tok = g_tok[e * NTOK + row];
                float w   = g_wt [e * NTOK + row];
                float* orow = out + (size_t)tok * DIM + n0 + nw;
#pragma unroll
                for (int nj = 0; nj < 4; nj++) {
                    int c = nj * 8 + (l & 3) * 2;
                    atomicAdd(&orow[c],     w * acc[mt][nj][hf * 2 + 0]);
                    atomicAdd(&orow[c + 1], w * acc[mt][nj][hf * 2 + 1]);
                }
            }
        }
    }
}

// ---------------------------------------------------------------------------
// Launch
// ---------------------------------------------------------------------------
extern "C" void kernel_launch(void* const* d_in, const int* in_sizes, int n_in,
                              void* d_out, int out_size) {
    const float* x  = (const float*)d_in[0];
    const float* Wg = (const float*)d_in[1];
    const float* W1 = (const float*)d_in[2];
    const float* W3 = (const float*)d_in[3];
    const float* W2 = (const float*)d_in[4];
    float* out = (float*)d_out;

    cudaFuncSetAttribute(ffn1_kernel,
        cudaFuncAttributeMaxDynamicSharedMemorySize, 3 * F1_STAGE);
    cudaFuncSetAttribute(ffn2_kernel,
        cudaFuncAttributeMaxDynamicSharedMemorySize, 3 * F2_STAGE);

    zero_kernel<<<1024, 256>>>(out, out_size / 4);
    cvtw_kernel<<<3 * 2048, 256>>>((const float4*)W1, (const float4*)W3,
                                   (const float4*)W2);
    route_kernel<<<NTOK / 8, 256>>>((const float4*)x, Wg);

    dim3 g1(HID / 64, NTOK / 128, NE);    // 32 x 32 x 8
    ffn1_kernel<<<g1, 256, 3 * F1_STAGE>>>();

    dim3 g2(DIM / 64, NTOK / 128, NE);    // 16 x 32 x 8
    ffn2_kernel<<<g2, 256, 3 * F2_STAGE>>>(out);
}

// round 8
// speedup vs baseline: 1.4728x; 1.3379x over previous
#include <cuda_runtime.h>
#include <cuda_fp16.h>
#include <math.h>
#include <stdint.h>

#define NTOK 4096
#define DIM  1024
#define HID  2048
#define NE   8

// ---------------------------------------------------------------------------
// Helpers
// ---------------------------------------------------------------------------
__device__ __forceinline__ uint32_t smem_to_u32(const void* p) {
    uint32_t a;
    asm("{ .reg .u64 t; cvta.to.shared.u64 t, %1; cvt.u32.u64 %0, t; }"
        : "=r"(a) : "l"(p));
    return a;
}

#define SWZ(rel)   ((rel) ^ (((rel) >> 3) & 0x70))   // 128B-row swizzle
#define SWZ64(rel) ((rel) ^ (((rel) >> 3) & 0x30))   // 64B-row swizzle

#define CP_ASYNC(dst, src, sz) \
    asm volatile("cp.async.cg.shared.global [%0], [%1], 16, %2;" \
        :: "r"(dst), "l"(src), "r"(sz))
#define CP_COMMIT() asm volatile("cp.async.commit_group;")
#define CP_WAIT(N)  asm volatile("cp.async.wait_group %0;" :: "n"(N))

__device__ __forceinline__ void ldsm_x4(uint32_t addr, uint32_t* r) {
    asm volatile("ldmatrix.sync.aligned.m8n8.x4.shared.b16 {%0,%1,%2,%3}, [%4];"
        : "=r"(r[0]), "=r"(r[1]), "=r"(r[2]), "=r"(r[3]) : "r"(addr));
}
__device__ __forceinline__ void ldsm_x4_t(uint32_t addr, uint32_t* r) {
    asm volatile("ldmatrix.sync.aligned.m8n8.x4.trans.shared.b16 {%0,%1,%2,%3}, [%4];"
        : "=r"(r[0]), "=r"(r[1]), "=r"(r[2]), "=r"(r[3]) : "r"(addr));
}
__device__ __forceinline__ void mma_f16(float* d, const uint32_t* a, const uint32_t* b) {
    asm volatile(
        "mma.sync.aligned.m16n8k16.row.col.f32.f16.f16.f32 "
        "{%0,%1,%2,%3}, {%4,%5,%6,%7}, {%8,%9}, {%0,%1,%2,%3};"
        : "+f"(d[0]), "+f"(d[1]), "+f"(d[2]), "+f"(d[3])
        : "r"(a[0]), "r"(a[1]), "r"(a[2]), "r"(a[3]), "r"(b[0]), "r"(b[1]));
}

__device__ __forceinline__ void cvt_hl(float f, __half& h, __half& l) {
    h = __float2half_rn(f);
    l = __float2half_rn(f - __half2float(h));
}
__device__ __forceinline__ uint32_t pack2(__half a, __half b) {
    __half2 t = __halves2half2(a, b);
    uint32_t r; memcpy(&r, &t, 4); return r;
}
// float4 -> packed hi uint2 / lo uint2 (fp16)
__device__ __forceinline__ void cvt4(float4 f, uint2& hv, uint2& lv) {
    __half h0,l0,h1,l1,h2,l2,h3,l3;
    cvt_hl(f.x, h0, l0); cvt_hl(f.y, h1, l1);
    cvt_hl(f.z, h2, l2); cvt_hl(f.w, h3, l3);
    hv.x = pack2(h0, h1); hv.y = pack2(h2, h3);
    lv.x = pack2(l0, l1); lv.y = pack2(l2, l3);
}
// float4 -> packed fp16 hi only
__device__ __forceinline__ uint2 cvt4h(float4 f) {
    uint2 hv;
    hv.x = pack2(__float2half_rn(f.x), __float2half_rn(f.y));
    hv.y = pack2(__float2half_rn(f.z), __float2half_rn(f.w));
    return hv;
}

// ---------------------------------------------------------------------------
// Scratch (device globals)
// ---------------------------------------------------------------------------
__device__ int   g_counts[NE];
__device__ int   g_tok[NE * NTOK];
__device__ float g_wt[NE * NTOK];
__device__ __half g_x[(size_t)NTOK * DIM];                // activations fp16
__device__ __half g_w1h[(size_t)NE * DIM * HID];
__device__ __half g_w1l[(size_t)NE * DIM * HID];
__device__ __half g_w3h[(size_t)NE * DIM * HID];
__device__ __half g_w3l[(size_t)NE * DIM * HID];
__device__ __half g_w2h[(size_t)NE * HID * DIM];
__device__ __half g_w2l[(size_t)NE * HID * DIM];
__device__ __half g_h[(size_t)(2 * NTOK) * HID];          // hidden fp16

// ---------------------------------------------------------------------------
// K0: zero output + counts
// ---------------------------------------------------------------------------
__global__ void zero_kernel(float* __restrict__ out, int n4) {
    int idx = blockIdx.x * blockDim.x + threadIdx.x;
    if (idx < NE) g_counts[idx] = 0;
    float4 z = make_float4(0.f, 0.f, 0.f, 0.f);
    float4* o4 = (float4*)out;
    for (int i = idx; i < n4; i += gridDim.x * blockDim.x) o4[i] = z;
}

// ---------------------------------------------------------------------------
// K-cvt: all three weights fp32 -> fp16 hi/lo planes
// ---------------------------------------------------------------------------
__global__ void cvtw_kernel(const float4* __restrict__ W1,
                            const float4* __restrict__ W3,
                            const float4* __restrict__ W2) {
    const int n8   = NE * DIM * HID / 8;
    const int gper = gridDim.x / 3;
    int t  = blockIdx.x / gper;
    int bl = blockIdx.x % gper;
    const float4* s = (t == 0) ? W1 : ((t == 1) ? W3 : W2);
    __half* dh = (t == 0) ? g_w1h : ((t == 1) ? g_w3h : g_w2h);
    __half* dl = (t == 0) ? g_w1l : ((t == 1) ? g_w3l : g_w2l);
    for (int i = bl * blockDim.x + threadIdx.x; i < n8; i += gper * blockDim.x) {
        float4 a = s[2 * i], b = s[2 * i + 1];
        uint2 ha, la, hb, lb;
        cvt4(a, ha, la); cvt4(b, hb, lb);
        *(uint4*)(dh + (size_t)i * 8) = make_uint4(ha.x, ha.y, hb.x, hb.y);
        *(uint4*)(dl + (size_t)i * 8) = make_uint4(la.x, la.y, lb.x, lb.y);
    }
}

// ---------------------------------------------------------------------------
// K1: routing + x fp16 conversion fused (one warp/token)
// ---------------------------------------------------------------------------
__global__ void route_kernel(const float4* __restrict__ x4,
                             const float* __restrict__ Wg) {
    int warp = (blockIdx.x * blockDim.x + threadIdx.x) >> 5;
    int lane = threadIdx.x & 31;
    if (warp >= NTOK) return;

    float sc[NE];
#pragma unroll
    for (int e = 0; e < NE; e++) sc[e] = 0.f;

#pragma unroll
    for (int j = 0; j < 8; j++) {
        int i4 = j * 32 + lane;
        float4 xv = x4[(size_t)warp * (DIM / 4) + i4];
        *(uint2*)(g_x + (size_t)warp * DIM + i4 * 4) = cvt4h(xv);
        float xs[4] = {xv.x, xv.y, xv.z, xv.w};
#pragma unroll
        for (int c = 0; c < 4; c++) {
            int row = i4 * 4 + c;
#pragma unroll
            for (int e = 0; e < NE; e++)
                sc[e] += xs[c] * Wg[row * NE + e];
        }
    }
#pragma unroll
    for (int o = 16; o > 0; o >>= 1)
#pragma unroll
        for (int e = 0; e < NE; e++)
            sc[e] += __shfl_xor_sync(0xffffffffu, sc[e], o);

    if (lane == 0) {
        int i0 = 0; float s0 = sc[0];
#pragma unroll
        for (int e = 1; e < NE; e++) if (sc[e] > s0) { s0 = sc[e]; i0 = e; }
        int i1 = -1; float s1 = -INFINITY;
#pragma unroll
        for (int e = 0; e < NE; e++)
            if (e != i0 && sc[e] > s1) { s1 = sc[e]; i1 = e; }
        float e1  = expf(s1 - s0);
        float inv = 1.f / (1.f + e1);
        int p0 = atomicAdd(&g_counts[i0], 1);
        g_tok[i0 * NTOK + p0] = warp;
        g_wt [i0 * NTOK + p0] = inv;
        int p1 = atomicAdd(&g_counts[i1], 1);
        g_tok[i1 * NTOK + p1] = warp;
        g_wt [i1 * NTOK + p1] = e1 * inv;
    }
}

__device__ __forceinline__ int expert_base(int e) {
    int b = 0;
#pragma unroll
    for (int j = 0; j < NE; j++) if (j < e) b += g_counts[j];
    return b;
}

// ---------------------------------------------------------------------------
// K3: FFN1 — fp16 2-pass. BM=128, BN=64, BK=32, 256 thr, 2 CTAs/SM, 3-stage.
// A: 128x32 fp16 single plane, 64B rows, SW64.  (8KB)
// B: 4 planes (W1h,W1l,W3h,W3l), 32k x 64n fp16, 128B rows, SW128. (16KB)
// Stage 24KB; x3 = 72KB dynamic.
// Loop: wait(1) -> barrier -> mma(it) -> load(it+2) -> commit.
// ---------------------------------------------------------------------------
#define F1_STAGE 24576
#define F2_STAGE 16384

__global__ __launch_bounds__(256, 2) void ffn1_kernel() {
    extern __shared__ char sm[];
    __shared__ int s_tok[128];

    int e   = blockIdx.z;
    int cnt = g_counts[e];
    int m0  = blockIdx.y * 128;
    if (m0 >= cnt) return;
    int n0   = blockIdx.x * 64;
    int base = expert_base(e);

    int tid = threadIdx.x, wid = tid >> 5, l = tid & 31;
    int mw = (wid >> 1) * 32, nw = (wid & 1) * 32;

    if (tid < 128) {
        int mg = m0 + tid;
        s_tok[tid] = (mg < cnt) ? g_tok[e * NTOK + mg] : -1;
    }
    __syncthreads();

    uint32_t sbase = smem_to_u32(sm);
    size_t eoffW = (size_t)e * DIM * HID;

    auto load_tile = [&](int it, int b) {
        int kb = it * 32;
        uint32_t abase = sbase + b * F1_STAGE;
        uint32_t bbase = abase + 8192;
        // A: 512 chunks of 16B (128 rows x 4)
#pragma unroll
        for (int j = 0; j < 2; j++) {
            int c = tid + j * 256;
            int row = c >> 2, cc = c & 3;
            int tok = s_tok[row];
            const void* src = g_x + ((size_t)(tok < 0 ? 0 : tok) * DIM + kb + cc * 8);
            uint32_t dst = abase + SWZ64((uint32_t)(row * 64 + cc * 16));
            int sz = (tok < 0) ? 0 : 16;
            CP_ASYNC(dst, src, sz);
        }
        // B: 1024 chunks over 4 planes
#pragma unroll
        for (int j = 0; j < 4; j++) {
            int c = tid + j * 256;
            int p = c >> 8, w = c & 255;
            int kr = w >> 3, n = (w & 7) * 8;
            const __half* sp;
            if      (p == 0) sp = g_w1h;
            else if (p == 1) sp = g_w1l;
            else if (p == 2) sp = g_w3h;
            else             sp = g_w3l;
            const void* src = sp + (eoffW + (size_t)(kb + kr) * HID + n0 + n);
            uint32_t dst = bbase + p * 4096 + SWZ((uint32_t)(kr * 128 + n * 2));
            CP_ASYNC(dst, src, 16);
        }
    };

    float acc1[2][4][4] = {};
    float acc3[2][4][4] = {};

    const int NIT = DIM / 32;
    load_tile(0, 0); CP_COMMIT();
    load_tile(1, 1); CP_COMMIT();

    for (int it = 0; it < NIT; it++) {
        CP_WAIT(1);
        __syncthreads();

        uint32_t aB = sbase + (it % 3) * F1_STAGE;
        uint32_t bB = aB + 8192;
        uint32_t b1h = bB + 0 * 4096, b1l = bB + 1 * 4096;
        uint32_t b3h = bB + 2 * 4096, b3l = bB + 3 * 4096;

#pragma unroll
        for (int ks = 0; ks < 2; ks++) {
            uint32_t a[2][4];
#pragma unroll
            for (int mt = 0; mt < 2; mt++) {
                int row  = mw + mt * 16 + ((l >> 3) & 1) * 8 + (l & 7);
                int kbyt = ks * 32 + (l >> 4) * 16;
                ldsm_x4(aB + SWZ64((uint32_t)(row * 64 + kbyt)), a[mt]);
            }
            int krow = ks * 16 + ((l >> 3) & 1) * 8 + (l & 7);
            uint32_t rb0 = krow * 128 + (nw + (l >> 4) * 8) * 2;
            uint32_t rb1 = rb0 + 32;
            uint32_t s0 = SWZ(rb0), s1 = SWZ(rb1);

            {   // W1: acc1 += A*(W1h + W1l)
                uint32_t bh[8], bl[8];
                ldsm_x4_t(b1h + s0, bh); ldsm_x4_t(b1h + s1, bh + 4);
                ldsm_x4_t(b1l + s0, bl); ldsm_x4_t(b1l + s1, bl + 4);
#pragma unroll
                for (int mt = 0; mt < 2; mt++)
#pragma unroll
                    for (int nj = 0; nj < 4; nj++) {
                        mma_f16(acc1[mt][nj], a[mt], &bh[nj * 2]);
                        mma_f16(acc1[mt][nj], a[mt], &bl[nj * 2]);
                    }
            }
            {   // W3: acc3 += A*(W3h + W3l)
                uint32_t bh[8], bl[8];
                ldsm_x4_t(b3h + s0, bh); ldsm_x4_t(b3h + s1, bh + 4);
                ldsm_x4_t(b3l + s0, bl); ldsm_x4_t(b3l + s1, bl + 4);
#pragma unroll
                for (int mt = 0; mt < 2; mt++)
#pragma unroll
                    for (int nj = 0; nj < 4; nj++) {
                        mma_f16(acc3[mt][nj], a[mt], &bh[nj * 2]);
                        mma_f16(acc3[mt][nj], a[mt], &bl[nj * 2]);
                    }
            }
        }

        if (it + 2 < NIT) load_tile(it + 2, (it + 2) % 3);
        CP_COMMIT();
    }

    // ---- epilogue: SwiGLU -> g_h (fp16) ----
#pragma unroll
    for (int mt = 0; mt < 2; mt++) {
#pragma unroll
        for (int hf = 0; hf < 2; hf++) {
            int row = m0 + mw + mt * 16 + (l >> 2) + hf * 8;
            if (row < cnt) {
                size_t rb = (size_t)(base + row) * HID + n0 + nw;
#pragma unroll
                for (int nj = 0; nj < 4; nj++) {
                    float a0 = acc1[mt][nj][hf * 2 + 0];
                    float a1 = acc1[mt][nj][hf * 2 + 1];
                    float h0 = a0 / (1.f + __expf(-a0)) * acc3[mt][nj][hf * 2 + 0];
                    float h1 = a1 / (1.f + __expf(-a1)) * acc3[mt][nj][hf * 2 + 1];
                    int c = nj * 8 + (l & 3) * 2;
                    *(uint32_t*)(g_h + rb + c) =
                        pack2(__float2half_rn(h0), __float2half_rn(h1));
                }
            }
        }
    }
}

// ---------------------------------------------------------------------------
// K4: FFN2 — fp16 2-pass. BM=128, BN=64, BK=32, 256 thr, 2 CTAs/SM, 3-stage.
// A: 128x32 fp16 (8KB, SW64). B: 2 planes (W2h,W2l) 4KB each. Stage 16KB x3.
// ---------------------------------------------------------------------------
__global__ __launch_bounds__(256, 2) void ffn2_kernel(float* __restrict__ out) {
    extern __shared__ char sm[];

    int e   = blockIdx.z;
    int cnt = g_counts[e];
    int m0  = blockIdx.y * 128;
    if (m0 >= cnt) return;
    int n0   = blockIdx.x * 64;
    int base = expert_base(e);

    int tid = threadIdx.x, wid = tid >> 5, l = tid & 31;
    int mw = (wid >> 1) * 32, nw = (wid & 1) * 32;

    uint32_t sbase = smem_to_u32(sm);
    size_t eoffW = (size_t)e * HID * DIM;

    auto load_tile = [&](int it, int b) {
        int kb = it * 32;
        uint32_t abase = sbase + b * F2_STAGE;
        uint32_t bbase = abase + 8192;
#pragma unroll
        for (int j = 0; j < 2; j++) {
            int c = tid + j * 256;
            int row = c >> 2, cc = c & 3;
            int mg = m0 + row;
            bool v = mg < cnt;
            const void* src = g_h + ((size_t)(v ? base + mg : 0) * HID + kb + cc * 8);
            uint32_t dst = abase + SWZ64((uint32_t)(row * 64 + cc * 16));
            int sz = v ? 16 : 0;
            CP_ASYNC(dst, src, sz);
        }
#pragma unroll
        for (int j = 0; j < 2; j++) {
            int c = tid + j * 256;
            int p = c >> 8, w = c & 255;
            int kr = w >> 3, n = (w & 7) * 8;
            const __half* sp = p ? g_w2l : g_w2h;
            const void* src = sp + (eoffW + (size_t)(kb + kr) * DIM + n0 + n);
            uint32_t dst = bbase + p * 4096 + SWZ((uint32_t)(kr * 128 + n * 2));
            CP_ASYNC(dst, src, 16);
        }
    };

    float acc[2][4][4] = {};

    const int NIT = HID / 32;
    load_tile(0, 0); CP_COMMIT();
    load_tile(1, 1); CP_COMMIT();

    for (int it = 0; it < NIT; it++) {
        CP_WAIT(1);
        __syncthreads();

        uint32_t aB = sbase + (it % 3) * F2_STAGE;
        uint32_t bB = aB + 8192;
        uint32_t bH = bB, bL = bB + 4096;

#pragma unroll
        for (int ks = 0; ks < 2; ks++) {
            uint32_t a[2][4];
#pragma unroll
            for (int mt = 0; mt < 2; mt++) {
                int row  = mw + mt * 16 + ((l >> 3) & 1) * 8 + (l & 7);
                int kbyt = ks * 32 + (l >> 4) * 16;
                ldsm_x4(aB + SWZ64((uint32_t)(row * 64 + kbyt)), a[mt]);
            }
            int krow = ks * 16 + ((l >> 3) & 1) * 8 + (l & 7);
            uint32_t rb0 = krow * 128 + (nw + (l >> 4) * 8) * 2;
            uint32_t rb1 = rb0 + 32;
            uint32_t s0 = SWZ(rb0), s1 = SWZ(rb1);

            uint32_t bh[8], bl[8];
            ldsm_x4_t(bH + s0, bh); ldsm_x4_t(bH + s1, bh + 4);
            ldsm_x4_t(bL + s0, bl); ldsm_x4_t(bL + s1, bl + 4);
#pragma unroll
            for (int mt = 0; mt < 2; mt++)
#pragma unroll
                for (int nj = 0; nj < 4; nj++) {
                    mma_f16(acc[mt][nj], a[mt], &bh[nj * 2]);
                    mma_f16(acc[mt][nj], a[mt], &bl[nj * 2]);
                }
        }

        if (it + 2 < NIT) load_tile(it + 2, (it + 2) % 3);
        CP_COMMIT();
    }

    // ---- epilogue: out[tok] += w * acc ----
#pragma unroll
    for (int mt = 0; mt < 2; mt++) {
#pragma unroll
        for (int hf = 0; hf < 2; hf++) {
            int row = m0 + mw + mt * 16 + (l >> 2) + hf * 8;
            if (row < cnt) {
                int   tok = g_tok[e * NTOK + row];
                float w   = g_wt [e * NTOK + row];
                float* orow = out + (size_t)tok * DIM + n0 + nw;
#pragma unroll
                for (int nj = 0; nj < 4; nj++) {
                    int c = nj * 8 + (l & 3) * 2;
                    atomicAdd(&orow[c],     w * acc[mt][nj][hf * 2 + 0]);
                    atomicAdd(&orow[c + 1], w * acc[mt][nj][hf * 2 + 1]);
                }
            }
        }
    }
}

// ---------------------------------------------------------------------------
// Launch
// ---------------------------------------------------------------------------
extern "C" void kernel_launch(void* const* d_in, const int* in_sizes, int n_in,
                              void* d_out, int out_size) {
    const float* x  = (const float*)d_in[0];
    const float* Wg = (const float*)d_in[1];
    const float* W1 = (const float*)d_in[2];
    const float* W3 = (const float*)d_in[3];
    const float* W2 = (const float*)d_in[4];
    float* out = (float*)d_out;

    cudaFuncSetAttribute(ffn1_kernel,
        cudaFuncAttributeMaxDynamicSharedMemorySize, 3 * F1_STAGE);
    cudaFuncSetAttribute(ffn2_kernel,
        cudaFuncAttributeMaxDynamicSharedMemorySize, 3 * F2_STAGE);

    zero_kernel<<<1024, 256>>>(out, out_size / 4);
    cvtw_kernel<<<3 * 2048, 256>>>((const float4*)W1, (const float4*)W3,
                                   (const float4*)W2);
    route_kernel<<<NTOK / 8, 256>>>((const float4*)x, Wg);

    dim3 g1(HID / 64, NTOK / 128, NE);    // 32 x 32 x 8
    ffn1_kernel<<<g1, 256, 3 * F1_STAGE>>>();

    dim3 g2(DIM / 64, NTOK / 128, NE);    // 16 x 32 x 8
    ffn2_kernel<<<g2, 256, 3 * F2_STAGE>>>(out);
}

// round 9
// speedup vs baseline: 2.0717x; 1.4067x over previous
#include <cuda_runtime.h>
#include <cuda_fp16.h>
#include <math.h>
#include <stdint.h>

#define NTOK 4096
#define DIM  1024
#define HID  2048
#define NE   8

// ---------------------------------------------------------------------------
// Helpers
// ---------------------------------------------------------------------------
__device__ __forceinline__ uint32_t smem_to_u32(const void* p) {
    uint32_t a;
    asm("{ .reg .u64 t; cvta.to.shared.u64 t, %1; cvt.u32.u64 %0, t; }"
        : "=r"(a) : "l"(p));
    return a;
}

#define SWZ(rel)   ((rel) ^ (((rel) >> 3) & 0x70))   // 128B-row swizzle
#define SWZ64(rel) ((rel) ^ (((rel) >> 3) & 0x30))   // 64B-row swizzle

#define CP_ASYNC(dst, src, sz) \
    asm volatile("cp.async.cg.shared.global [%0], [%1], 16, %2;" \
        :: "r"(dst), "l"(src), "r"(sz))
#define CP_COMMIT() asm volatile("cp.async.commit_group;")
#define CP_WAIT(N)  asm volatile("cp.async.wait_group %0;" :: "n"(N))

__device__ __forceinline__ void ldsm_x4(uint32_t addr, uint32_t* r) {
    asm volatile("ldmatrix.sync.aligned.m8n8.x4.shared.b16 {%0,%1,%2,%3}, [%4];"
        : "=r"(r[0]), "=r"(r[1]), "=r"(r[2]), "=r"(r[3]) : "r"(addr));
}
__device__ __forceinline__ void ldsm_x4_t(uint32_t addr, uint32_t* r) {
    asm volatile("ldmatrix.sync.aligned.m8n8.x4.trans.shared.b16 {%0,%1,%2,%3}, [%4];"
        : "=r"(r[0]), "=r"(r[1]), "=r"(r[2]), "=r"(r[3]) : "r"(addr));
}
__device__ __forceinline__ void mma_f16(float* d, const uint32_t* a, const uint32_t* b) {
    asm volatile(
        "mma.sync.aligned.m16n8k16.row.col.f32.f16.f16.f32 "
        "{%0,%1,%2,%3}, {%4,%5,%6,%7}, {%8,%9}, {%0,%1,%2,%3};"
        : "+f"(d[0]), "+f"(d[1]), "+f"(d[2]), "+f"(d[3])
        : "r"(a[0]), "r"(a[1]), "r"(a[2]), "r"(a[3]), "r"(b[0]), "r"(b[1]));
}

__device__ __forceinline__ uint32_t pack2(__half a, __half b) {
    __half2 t = __halves2half2(a, b);
    uint32_t r; memcpy(&r, &t, 4); return r;
}
// float4 -> packed fp16
__device__ __forceinline__ uint2 cvt4h(float4 f) {
    uint2 hv;
    hv.x = pack2(__float2half_rn(f.x), __float2half_rn(f.y));
    hv.y = pack2(__float2half_rn(f.z), __float2half_rn(f.w));
    return hv;
}

// ---------------------------------------------------------------------------
// Scratch (device globals)
// ---------------------------------------------------------------------------
__device__ int   g_counts[NE];
__device__ int   g_tok[NE * NTOK];
__device__ float g_wt[NE * NTOK];
__device__ __half g_x[(size_t)NTOK * DIM];           // activations fp16
__device__ __half g_w1[(size_t)NE * DIM * HID];
__device__ __half g_w3[(size_t)NE * DIM * HID];
__device__ __half g_w2[(size_t)NE * HID * DIM];
__device__ __half g_h[(size_t)(2 * NTOK) * HID];     // hidden fp16

// ---------------------------------------------------------------------------
// K0: zero output + counts
// ---------------------------------------------------------------------------
__global__ void zero_kernel(float* __restrict__ out, int n4) {
    int idx = blockIdx.x * blockDim.x + threadIdx.x;
    if (idx < NE) g_counts[idx] = 0;
    float4 z = make_float4(0.f, 0.f, 0.f, 0.f);
    float4* o4 = (float4*)out;
    for (int i = idx; i < n4; i += gridDim.x * blockDim.x) o4[i] = z;
}

// ---------------------------------------------------------------------------
// K-cvt: all three weights fp32 -> fp16 (single plane), 16B stores
// ---------------------------------------------------------------------------
__global__ void cvtw_kernel(const float4* __restrict__ W1,
                            const float4* __restrict__ W3,
                            const float4* __restrict__ W2) {
    const int n8   = NE * DIM * HID / 8;
    const int gper = gridDim.x / 3;
    int t  = blockIdx.x / gper;
    int bl = blockIdx.x % gper;
    const float4* s = (t == 0) ? W1 : ((t == 1) ? W3 : W2);
    __half* d = (t == 0) ? g_w1 : ((t == 1) ? g_w3 : g_w2);
    for (int i = bl * blockDim.x + threadIdx.x; i < n8; i += gper * blockDim.x) {
        float4 a = s[2 * i], b = s[2 * i + 1];
        uint2 ha = cvt4h(a), hb = cvt4h(b);
        *(uint4*)(d + (size_t)i * 8) = make_uint4(ha.x, ha.y, hb.x, hb.y);
    }
}

// ---------------------------------------------------------------------------
// K1: routing + x fp16 conversion fused (one warp/token)
// ---------------------------------------------------------------------------
__global__ void route_kernel(const float4* __restrict__ x4,
                             const float* __restrict__ Wg) {
    int warp = (blockIdx.x * blockDim.x + threadIdx.x) >> 5;
    int lane = threadIdx.x & 31;
    if (warp >= NTOK) return;

    float sc[NE];
#pragma unroll
    for (int e = 0; e < NE; e++) sc[e] = 0.f;

#pragma unroll
    for (int j = 0; j < 8; j++) {
        int i4 = j * 32 + lane;
        float4 xv = x4[(size_t)warp * (DIM / 4) + i4];
        *(uint2*)(g_x + (size_t)warp * DIM + i4 * 4) = cvt4h(xv);
        float xs[4] = {xv.x, xv.y, xv.z, xv.w};
#pragma unroll
        for (int c = 0; c < 4; c++) {
            int row = i4 * 4 + c;
#pragma unroll
            for (int e = 0; e < NE; e++)
                sc[e] += xs[c] * Wg[row * NE + e];
        }
    }
#pragma unroll
    for (int o = 16; o > 0; o >>= 1)
#pragma unroll
        for (int e = 0; e < NE; e++)
            sc[e] += __shfl_xor_sync(0xffffffffu, sc[e], o);

    if (lane == 0) {
        int i0 = 0; float s0 = sc[0];
#pragma unroll
        for (int e = 1; e < NE; e++) if (sc[e] > s0) { s0 = sc[e]; i0 = e; }
        int i1 = -1; float s1 = -INFINITY;
#pragma unroll
        for (int e = 0; e < NE; e++)
            if (e != i0 && sc[e] > s1) { s1 = sc[e]; i1 = e; }
        float e1  = expf(s1 - s0);
        float inv = 1.f / (1.f + e1);
        int p0 = atomicAdd(&g_counts[i0], 1);
        g_tok[i0 * NTOK + p0] = warp;
        g_wt [i0 * NTOK + p0] = inv;
        int p1 = atomicAdd(&g_counts[i1], 1);
        g_tok[i1 * NTOK + p1] = warp;
        g_wt [i1 * NTOK + p1] = e1 * inv;
    }
}

__device__ __forceinline__ int expert_base(int e) {
    int b = 0;
#pragma unroll
    for (int j = 0; j < NE; j++) if (j < e) b += g_counts[j];
    return b;
}

// ---------------------------------------------------------------------------
// K3: FFN1 — fp16 single-pass. BM=128, BN=64, BK=32, 256 thr, 2 CTAs/SM.
// A: 128x32 fp16, 64B rows SW64 (8KB). B: W1,W3 planes 32x64 fp16, SW128 (8KB).
// Stage 16KB; x3 = 48KB dynamic.
// Loop: wait(1) -> barrier -> mma(it) -> load(it+2) -> commit.
// ---------------------------------------------------------------------------
#define F1_STAGE 16384
#define F2_STAGE 12288

__global__ __launch_bounds__(256, 2) void ffn1_kernel() {
    extern __shared__ char sm[];
    __shared__ int s_tok[128];

    int e   = blockIdx.z;
    int cnt = g_counts[e];
    int m0  = blockIdx.y * 128;
    if (m0 >= cnt) return;
    int n0   = blockIdx.x * 64;
    int base = expert_base(e);

    int tid = threadIdx.x, wid = tid >> 5, l = tid & 31;
    int mw = (wid >> 1) * 32, nw = (wid & 1) * 32;

    if (tid < 128) {
        int mg = m0 + tid;
        s_tok[tid] = (mg < cnt) ? g_tok[e * NTOK + mg] : -1;
    }
    __syncthreads();

    uint32_t sbase = smem_to_u32(sm);
    size_t eoffW = (size_t)e * DIM * HID;

    auto load_tile = [&](int it, int b) {
        int kb = it * 32;
        uint32_t abase = sbase + b * F1_STAGE;
        uint32_t bbase = abase + 8192;
        // A: 512 chunks of 16B (128 rows x 4)
#pragma unroll
        for (int j = 0; j < 2; j++) {
            int c = tid + j * 256;
            int row = c >> 2, cc = c & 3;
            int tok = s_tok[row];
            const void* src = g_x + ((size_t)(tok < 0 ? 0 : tok) * DIM + kb + cc * 8);
            uint32_t dst = abase + SWZ64((uint32_t)(row * 64 + cc * 16));
            int sz = (tok < 0) ? 0 : 16;
            CP_ASYNC(dst, src, sz);
        }
        // B: 512 chunks over 2 planes (W1, W3), 32k x 64n each
#pragma unroll
        for (int j = 0; j < 2; j++) {
            int c = tid + j * 256;
            int p = c >> 8, w = c & 255;
            int kr = w >> 3, n = (w & 7) * 8;
            const __half* sp = p ? g_w3 : g_w1;
            const void* src = sp + (eoffW + (size_t)(kb + kr) * HID + n0 + n);
            uint32_t dst = bbase + p * 4096 + SWZ((uint32_t)(kr * 128 + n * 2));
            CP_ASYNC(dst, src, 16);
        }
    };

    float acc1[2][4][4] = {};
    float acc3[2][4][4] = {};

    const int NIT = DIM / 32;
    load_tile(0, 0); CP_COMMIT();
    load_tile(1, 1); CP_COMMIT();

    for (int it = 0; it < NIT; it++) {
        CP_WAIT(1);
        __syncthreads();

        uint32_t aB = sbase + (it % 3) * F1_STAGE;
        uint32_t bB = aB + 8192;
        uint32_t b1 = bB, b3 = bB + 4096;

#pragma unroll
        for (int ks = 0; ks < 2; ks++) {
            uint32_t a[2][4];
#pragma unroll
            for (int mt = 0; mt < 2; mt++) {
                int row  = mw + mt * 16 + ((l >> 3) & 1) * 8 + (l & 7);
                int kbyt = ks * 32 + (l >> 4) * 16;
                ldsm_x4(aB + SWZ64((uint32_t)(row * 64 + kbyt)), a[mt]);
            }
            int krow = ks * 16 + ((l >> 3) & 1) * 8 + (l & 7);
            uint32_t rb0 = krow * 128 + (nw + (l >> 4) * 8) * 2;
            uint32_t rb1 = rb0 + 32;
            uint32_t s0 = SWZ(rb0), s1 = SWZ(rb1);

            {   // W1
                uint32_t bh[8];
                ldsm_x4_t(b1 + s0, bh); ldsm_x4_t(b1 + s1, bh + 4);
#pragma unroll
                for (int mt = 0; mt < 2; mt++)
#pragma unroll
                    for (int nj = 0; nj < 4; nj++)
                        mma_f16(acc1[mt][nj], a[mt], &bh[nj * 2]);
            }
            {   // W3
                uint32_t bh[8];
                ldsm_x4_t(b3 + s0, bh); ldsm_x4_t(b3 + s1, bh + 4);
#pragma unroll
                for (int mt = 0; mt < 2; mt++)
#pragma unroll
                    for (int nj = 0; nj < 4; nj++)
                        mma_f16(acc3[mt][nj], a[mt], &bh[nj * 2]);
            }
        }

        if (it + 2 < NIT) load_tile(it + 2, (it + 2) % 3);
        CP_COMMIT();
    }

    // ---- epilogue: SwiGLU -> g_h (fp16) ----
#pragma unroll
    for (int mt = 0; mt < 2; mt++) {
#pragma unroll
        for (int hf = 0; hf < 2; hf++) {
            int row = m0 + mw + mt * 16 + (l >> 2) + hf * 8;
            if (row < cnt) {
                size_t rb = (size_t)(base + row) * HID + n0 + nw;
#pragma unroll
                for (int nj = 0; nj < 4; nj++) {
                    float a0 = acc1[mt][nj][hf * 2 + 0];
                    float a1 = acc1[mt][nj][hf * 2 + 1];
                    float h0 = a0 / (1.f + __expf(-a0)) * acc3[mt][nj][hf * 2 + 0];
                    float h1 = a1 / (1.f + __expf(-a1)) * acc3[mt][nj][hf * 2 + 1];
                    int c = nj * 8 + (l & 3) * 2;
                    *(uint32_t*)(g_h + rb + c) =
                        pack2(__float2half_rn(h0), __float2half_rn(h1));
                }
            }
        }
    }
}

// ---------------------------------------------------------------------------
// K4: FFN2 — fp16 single-pass. BM=128, BN=64, BK=32, 256 thr, 2 CTAs/SM.
// A: 8KB SW64. B: W2 plane 4KB. Stage 12KB; x3 = 36KB dynamic.
// ---------------------------------------------------------------------------
__global__ __launch_bounds__(256, 2) void ffn2_kernel(float* __restrict__ out) {
    extern __shared__ char sm[];

    int e   = blockIdx.z;
    int cnt = g_counts[e];
    int m0  = blockIdx.y * 128;
    if (m0 >= cnt) return;
    int n0   = blockIdx.x * 64;
    int base = expert_base(e);

    int tid = threadIdx.x, wid = tid >> 5, l = tid & 31;
    int mw = (wid >> 1) * 32, nw = (wid & 1) * 32;

    uint32_t sbase = smem_to_u32(sm);
    size_t eoffW = (size_t)e * HID * DIM;

    auto load_tile = [&](int it, int b) {
        int kb = it * 32;
        uint32_t abase = sbase + b * F2_STAGE;
        uint32_t bbase = abase + 8192;
#pragma unroll
        for (int j = 0; j < 2; j++) {
            int c = tid + j * 256;
            int row = c >> 2, cc = c & 3;
            int mg = m0 + row;
            bool v = mg < cnt;
            const void* src = g_h + ((size_t)(v ? base + mg : 0) * HID + kb + cc * 8);
            uint32_t dst = abase + SWZ64((uint32_t)(row * 64 + cc * 16));
            int sz = v ? 16 : 0;
            CP_ASYNC(dst, src, sz);
        }
        {   // B: 256 chunks, single W2 plane
            int c = tid;
            int kr = c >> 3, n = (c & 7) * 8;
            const void* src = g_w2 + (eoffW + (size_t)(kb + kr) * DIM + n0 + n);
            uint32_t dst = bbase + SWZ((uint32_t)(kr * 128 + n * 2));
            CP_ASYNC(dst, src, 16);
        }
    };

    float acc[2][4][4] = {};

    const int NIT = HID / 32;
    load_tile(0, 0); CP_COMMIT();
    load_tile(1, 1); CP_COMMIT();

    for (int it = 0; it < NIT; it++) {
        CP_WAIT(1);
        __syncthreads();

        uint32_t aB = sbase + (it % 3) * F2_STAGE;
        uint32_t bB = aB + 8192;

#pragma unroll
        for (int ks = 0; ks < 2; ks++) {
            uint32_t a[2][4];
#pragma unroll
            for (int mt = 0; mt < 2; mt++) {
                int row  = mw + mt * 16 + ((l >> 3) & 1) * 8 + (l & 7);
                int kbyt = ks * 32 + (l >> 4) * 16;
                ldsm_x4(aB + SWZ64((uint32_t)(row * 64 + kbyt)), a[mt]);
            }
            int krow = ks * 16 + ((l >> 3) & 1) * 8 + (l & 7);
            uint32_t rb0 = krow * 128 + (nw + (l >> 4) * 8) * 2;
            uint32_t rb1 = rb0 + 32;
            uint32_t s0 = SWZ(rb0), s1 = SWZ(rb1);

            uint32_t bh[8];
            ldsm_x4_t(bB + s0, bh); ldsm_x4_t(bB + s1, bh + 4);
#pragma unroll
            for (int mt = 0; mt < 2; mt++)
#pragma unroll
                for (int nj = 0; nj < 4; nj++)
                    mma_f16(acc[mt][nj], a[mt], &bh[nj * 2]);
        }

        if (it + 2 < NIT) load_tile(it + 2, (it + 2) % 3);
        CP_COMMIT();
    }

    // ---- epilogue: out[tok] += w * acc ----
#pragma unroll
    for (int mt = 0; mt < 2; mt++) {
#pragma unroll
        for (int hf = 0; hf < 2; hf++) {
            int row = m0 + mw + mt * 16 + (l >> 2) + hf * 8;
            if (row < cnt) {
                int   tok = g_tok[e * NTOK + row];
                float w   = g_wt [e * NTOK + row];
                float* orow = out + (size_t)tok * DIM + n0 + nw;
#pragma unroll
                for (int nj = 0; nj < 4; nj++) {
                    int c = nj * 8 + (l & 3) * 2;
                    atomicAdd(&orow[c],     w * acc[mt][nj][hf * 2 + 0]);
                    atomicAdd(&orow[c + 1], w * acc[mt][nj][hf * 2 + 1]);
                }
            }
        }
    }
}

// ---------------------------------------------------------------------------
// Launch
// ---------------------------------------------------------------------------
extern "C" void kernel_launch(void* const* d_in, const int* in_sizes, int n_in,
                              void* d_out, int out_size) {
    const float* x  = (const float*)d_in[0];
    const float* Wg = (const float*)d_in[1];
    const float* W1 = (const float*)d_in[2];
    const float* W3 = (const float*)d_in[3];
    const float* W2 = (const float*)d_in[4];
    float* out = (float*)d_out;

    cudaFuncSetAttribute(ffn1_kernel,
        cudaFuncAttributeMaxDynamicSharedMemorySize, 3 * F1_STAGE);
    cudaFuncSetAttribute(ffn2_kernel,
        cudaFuncAttributeMaxDynamicSharedMemorySize, 3 * F2_STAGE);

    zero_kernel<<<1024, 256>>>(out, out_size / 4);
    cvtw_kernel<<<3 * 2048, 256>>>((const float4*)W1, (const float4*)W3,
                                   (const float4*)W2);
    route_kernel<<<NTOK / 8, 256>>>((const float4*)x, Wg);

    dim3 g1(HID / 64, NTOK / 128, NE);    // 32 x 32 x 8
    ffn1_kernel<<<g1, 256, 3 * F1_STAGE>>>();

    dim3 g2(DIM / 64, NTOK / 128, NE);    // 16 x 32 x 8
    ffn2_kernel<<<g2, 256, 3 * F2_STAGE>>>(out);
}

// round 11
// speedup vs baseline: 2.1969x; 1.0604x over previous
#include <cuda_runtime.h>
#include <cuda_fp16.h>
#include <math.h>
#include <stdint.h>

#define NTOK 4096
#define DIM  1024
#define HID  2048
#define NE   8

// ---------------------------------------------------------------------------
// Helpers
// ---------------------------------------------------------------------------
__device__ __forceinline__ uint32_t smem_to_u32(const void* p) {
    uint32_t a;
    asm("{ .reg .u64 t; cvta.to.shared.u64 t, %1; cvt.u32.u64 %0, t; }"
        : "=r"(a) : "l"(p));
    return a;
}

#define SWZ(rel) ((rel) ^ (((rel) >> 3) & 0x70))   // 128B-row swizzle

#define CP_ASYNC(dst, src, sz) \
    asm volatile("cp.async.cg.shared.global [%0], [%1], 16, %2;" \
        :: "r"(dst), "l"(src), "r"(sz))
#define CP_COMMIT() asm volatile("cp.async.commit_group;")
#define CP_WAIT(N)  asm volatile("cp.async.wait_group %0;" :: "n"(N))

__device__ __forceinline__ void ldsm_x4(uint32_t addr, uint32_t* r) {
    asm volatile("ldmatrix.sync.aligned.m8n8.x4.shared.b16 {%0,%1,%2,%3}, [%4];"
        : "=r"(r[0]), "=r"(r[1]), "=r"(r[2]), "=r"(r[3]) : "r"(addr));
}
__device__ __forceinline__ void ldsm_x4_t(uint32_t addr, uint32_t* r) {
    asm volatile("ldmatrix.sync.aligned.m8n8.x4.trans.shared.b16 {%0,%1,%2,%3}, [%4];"
        : "=r"(r[0]), "=r"(r[1]), "=r"(r[2]), "=r"(r[3]) : "r"(addr));
}
__device__ __forceinline__ void mma_f16(float* d, const uint32_t* a, const uint32_t* b) {
    asm volatile(
        "mma.sync.aligned.m16n8k16.row.col.f32.f16.f16.f32 "
        "{%0,%1,%2,%3}, {%4,%5,%6,%7}, {%8,%9}, {%0,%1,%2,%3};"
        : "+f"(d[0]), "+f"(d[1]), "+f"(d[2]), "+f"(d[3])
        : "r"(a[0]), "r"(a[1]), "r"(a[2]), "r"(a[3]), "r"(b[0]), "r"(b[1]));
}

__device__ __forceinline__ uint32_t pack2(__half a, __half b) {
    __half2 t = __halves2half2(a, b);
    uint32_t r; memcpy(&r, &t, 4); return r;
}
__device__ __forceinline__ uint2 cvt4h(float4 f) {
    uint2 hv;
    hv.x = pack2(__float2half_rn(f.x), __float2half_rn(f.y));
    hv.y = pack2(__float2half_rn(f.z), __float2half_rn(f.w));
    return hv;
}

// ---------------------------------------------------------------------------
// Scratch (device globals)
// ---------------------------------------------------------------------------
__device__ int   g_counts[NE];
__device__ int   g_tok[NE * NTOK];
__device__ float g_wt[NE * NTOK];
__device__ __half g_x[(size_t)NTOK * DIM];
__device__ __half g_w1[(size_t)NE * DIM * HID];
__device__ __half g_w3[(size_t)NE * DIM * HID];
__device__ __half g_w2[(size_t)NE * HID * DIM];
__device__ __half g_h[(size_t)(2 * NTOK) * HID];

// ---------------------------------------------------------------------------
// K0: prep — weights fp32 -> fp16 + zero out + zero counts (before route)
// ---------------------------------------------------------------------------
__global__ void prep_kernel(const float4* __restrict__ W1,
                            const float4* __restrict__ W3,
                            const float4* __restrict__ W2,
                            float4* __restrict__ out, int n4) {
    const int n8   = NE * DIM * HID / 8;
    const int gper = gridDim.x / 3;
    int t  = blockIdx.x / gper;
    int bl = blockIdx.x % gper;
    const float4* s = (t == 0) ? W1 : ((t == 1) ? W3 : W2);
    __half* d = (t == 0) ? g_w1 : ((t == 1) ? g_w3 : g_w2);
    for (int i = bl * blockDim.x + threadIdx.x; i < n8; i += gper * blockDim.x) {
        float4 a = s[2 * i], b = s[2 * i + 1];
        uint2 ha = cvt4h(a), hb = cvt4h(b);
        *(uint4*)(d + (size_t)i * 8) = make_uint4(ha.x, ha.y, hb.x, hb.y);
    }
    int gid = blockIdx.x * blockDim.x + threadIdx.x;
    if (gid < NE) g_counts[gid] = 0;
    float4 z = make_float4(0.f, 0.f, 0.f, 0.f);
    for (int i = gid; i < n4; i += gridDim.x * blockDim.x) out[i] = z;
}

// ---------------------------------------------------------------------------
// K1: routing + x fp16 conversion fused (one warp/token)
// ---------------------------------------------------------------------------
__global__ void route_kernel(const float4* __restrict__ x4,
                             const float* __restrict__ Wg) {
    int warp = (blockIdx.x * blockDim.x + threadIdx.x) >> 5;
    int lane = threadIdx.x & 31;
    if (warp >= NTOK) return;

    float sc[NE];
#pragma unroll
    for (int e = 0; e < NE; e++) sc[e] = 0.f;

#pragma unroll
    for (int j = 0; j < 8; j++) {
        int i4 = j * 32 + lane;
        float4 xv = x4[(size_t)warp * (DIM / 4) + i4];
        *(uint2*)(g_x + (size_t)warp * DIM + i4 * 4) = cvt4h(xv);
        float xs[4] = {xv.x, xv.y, xv.z, xv.w};
#pragma unroll
        for (int c = 0; c < 4; c++) {
            int row = i4 * 4 + c;
#pragma unroll
            for (int e = 0; e < NE; e++)
                sc[e] += xs[c] * Wg[row * NE + e];
        }
    }
#pragma unroll
    for (int o = 16; o > 0; o >>= 1)
#pragma unroll
        for (int e = 0; e < NE; e++)
            sc[e] += __shfl_xor_sync(0xffffffffu, sc[e], o);

    if (lane == 0) {
        int i0 = 0; float s0 = sc[0];
#pragma unroll
        for (int e = 1; e < NE; e++) if (sc[e] > s0) { s0 = sc[e]; i0 = e; }
        int i1 = -1; float s1 = -INFINITY;
#pragma unroll
        for (int e = 0; e < NE; e++)
            if (e != i0 && sc[e] > s1) { s1 = sc[e]; i1 = e; }
        float e1  = expf(s1 - s0);
        float inv = 1.f / (1.f + e1);
        int p0 = atomicAdd(&g_counts[i0], 1);
        g_tok[i0 * NTOK + p0] = warp;
        g_wt [i0 * NTOK + p0] = inv;
        int p1 = atomicAdd(&g_counts[i1], 1);
        g_tok[i1 * NTOK + p1] = warp;
        g_wt [i1 * NTOK + p1] = e1 * inv;
    }
}

__device__ __forceinline__ int expert_base(int e) {
    int b = 0;
#pragma unroll
    for (int j = 0; j < NE; j++) if (j < e) b += g_counts[j];
    return b;
}

// ---------------------------------------------------------------------------
// K3: FFN1 — fp16 single-pass, BK=64. BM=128, BN=64, 256 thr, 2 CTAs/SM.
// A: 128x64 fp16, 128B rows SW128 (16KB). B: W1,W3 planes 64k x 64n (8KB ea).
// Stage 32KB; x3 = 96KB dynamic. NIT = 16.
// Loop: wait(1) -> barrier -> mma(it, 4 ks) -> load(it+2) -> commit.
// ---------------------------------------------------------------------------
#define F1_STAGE 32768
#define F2_STAGE 24576

__global__ __launch_bounds__(256, 2) void ffn1_kernel() {
    extern __shared__ char sm[];
    __shared__ int s_tok[128];

    int e   = blockIdx.z;
    int cnt = g_counts[e];
    int m0  = blockIdx.y * 128;
    if (m0 >= cnt) return;
    int n0   = blockIdx.x * 64;
    int base = expert_base(e);

    int tid = threadIdx.x, wid = tid >> 5, l = tid & 31;
    int mw = (wid >> 1) * 32, nw = (wid & 1) * 32;

    if (tid < 128) {
        int mg = m0 + tid;
        s_tok[tid] = (mg < cnt) ? g_tok[e * NTOK + mg] : -1;
    }
    __syncthreads();

    uint32_t sbase = smem_to_u32(sm);
    size_t eoffW = (size_t)e * DIM * HID;

    auto load_tile = [&](int it, int b) {
        int kb = it * 64;
        uint32_t abase = sbase + b * F1_STAGE;
        uint32_t bbase = abase + 16384;
        // A: 1024 chunks of 16B (128 rows x 8)
#pragma unroll
        for (int j = 0; j < 4; j++) {
            int c = tid + j * 256;
            int row = c >> 3, cc = c & 7;
            int tok = s_tok[row];
            const void* src = g_x + ((size_t)(tok < 0 ? 0 : tok) * DIM + kb + cc * 8);
            uint32_t dst = abase + SWZ((uint32_t)(row * 128 + cc * 16));
            int sz = (tok < 0) ? 0 : 16;
            CP_ASYNC(dst, src, sz);
        }
        // B: 1024 chunks over 2 planes (W1, W3), 64k x 64n each
#pragma unroll
        for (int j = 0; j < 4; j++) {
            int c = tid + j * 256;
            int p = c >> 9, w = c & 511;
            int kr = w >> 3, n = (w & 7) * 8;
            const __half* sp = p ? g_w3 : g_w1;
            const void* src = sp + (eoffW + (size_t)(kb + kr) * HID + n0 + n);
            uint32_t dst = bbase + p * 8192 + SWZ((uint32_t)(kr * 128 + n * 2));
            CP_ASYNC(dst, src, 16);
        }
    };

    float acc1[2][4][4] = {};
    float acc3[2][4][4] = {};

    const int NIT = DIM / 64;
    load_tile(0, 0); CP_COMMIT();
    load_tile(1, 1); CP_COMMIT();

    for (int it = 0; it < NIT; it++) {
        CP_WAIT(1);
        __syncthreads();

        uint32_t aB = sbase + (it % 3) * F1_STAGE;
        uint32_t bB = aB + 16384;
        uint32_t b1 = bB, b3 = bB + 8192;

#pragma unroll
        for (int ks = 0; ks < 4; ks++) {
            uint32_t a[2][4];
#pragma unroll
            for (int mt = 0; mt < 2; mt++) {
                int row  = mw + mt * 16 + ((l >> 3) & 1) * 8 + (l & 7);
                int kbyt = ks * 32 + (l >> 4) * 16;
                ldsm_x4(aB + SWZ((uint32_t)(row * 128 + kbyt)), a[mt]);
            }
            int krow = ks * 16 + ((l >> 3) & 1) * 8 + (l & 7);
            uint32_t rb0 = krow * 128 + (nw + (l >> 4) * 8) * 2;
            uint32_t rb1 = rb0 + 32;
            uint32_t s0 = SWZ(rb0), s1 = SWZ(rb1);

            {   // W1
                uint32_t bh[8];
                ldsm_x4_t(b1 + s0, bh); ldsm_x4_t(b1 + s1, bh + 4);
#pragma unroll
                for (int mt = 0; mt < 2; mt++)
#pragma unroll
                    for (int nj = 0; nj < 4; nj++)
                        mma_f16(acc1[mt][nj], a[mt], &bh[nj * 2]);
            }
            {   // W3
                uint32_t bh[8];
                ldsm_x4_t(b3 + s0, bh); ldsm_x4_t(b3 + s1, bh + 4);
#pragma unroll
                for (int mt = 0; mt < 2; mt++)
#pragma unroll
                    for (int nj = 0; nj < 4; nj++)
                        mma_f16(acc3[mt][nj], a[mt], &bh[nj * 2]);
            }
        }

        if (it + 2 < NIT) load_tile(it + 2, (it + 2) % 3);
        CP_COMMIT();
    }

    // ---- epilogue: SwiGLU -> g_h (fp16) ----
#pragma unroll
    for (int mt = 0; mt < 2; mt++) {
#pragma unroll
        for (int hf = 0; hf < 2; hf++) {
            int row = m0 + mw + mt * 16 + (l >> 2) + hf * 8;
            if (row < cnt) {
                size_t rb = (size_t)(base + row) * HID + n0 + nw;
#pragma unroll
                for (int nj = 0; nj < 4; nj++) {
                    float a0 = acc1[mt][nj][hf * 2 + 0];
                    float a1 = acc1[mt][nj][hf * 2 + 1];
                    float h0 = a0 / (1.f + __expf(-a0)) * acc3[mt][nj][hf * 2 + 0];
                    float h1 = a1 / (1.f + __expf(-a1)) * acc3[mt][nj][hf * 2 + 1];
                    int c = nj * 8 + (l & 3) * 2;
                    *(uint32_t*)(g_h + rb + c) =
                        pack2(__float2half_rn(h0), __float2half_rn(h1));
                }
            }
        }
    }
}

// ---------------------------------------------------------------------------
// K4: FFN2 — fp16 single-pass, BK=64. BM=128, BN=64, 256 thr, 2 CTAs/SM.
// A: 16KB SW128. B: W2 64x64 (8KB). Stage 24KB; x3 = 72KB. NIT = 32.
// ---------------------------------------------------------------------------
__global__ __launch_bounds__(256, 2) void ffn2_kernel(float* __restrict__ out) {
    extern __shared__ char sm[];

    int e   = blockIdx.z;
    int cnt = g_counts[e];
    int m0  = blockIdx.y * 128;
    if (m0 >= cnt) return;
    int n0   = blockIdx.x * 64;
    int base = expert_base(e);

    int tid = threadIdx.x, wid = tid >> 5, l = tid & 31;
    int mw = (wid >> 1) * 32, nw = (wid & 1) * 32;

    uint32_t sbase = smem_to_u32(sm);
    size_t eoffW = (size_t)e * HID * DIM;

    auto load_tile = [&](int it, int b) {
        int kb = it * 64;
        uint32_t abase = sbase + b * F2_STAGE;
        uint32_t bbase = abase + 16384;
#pragma unroll
        for (int j = 0; j < 4; j++) {
            int c = tid + j * 256;
            int row = c >> 3, cc = c & 7;
            int mg = m0 + row;
            bool v = mg < cnt;
            const void* src = g_h + ((size_t)(v ? base + mg : 0) * HID + kb + cc * 8);
            uint32_t dst = abase + SWZ((uint32_t)(row * 128 + cc * 16));
            int sz = v ? 16 : 0;
            CP_ASYNC(dst, src, sz);
        }
#pragma unroll
        for (int j = 0; j < 2; j++) {
            int c = tid + j * 256;
            int kr = c >> 3, n = (c & 7) * 8;
            const void* src = g_w2 + (eoffW + (size_t)(kb + kr) * DIM + n0 + n);
            uint32_t dst = bbase + SWZ((uint32_t)(kr * 128 + n * 2));
            CP_ASYNC(dst, src, 16);
        }
    };

    float acc[2][4][4] = {};

    const int NIT = HID / 64;
    load_tile(0, 0); CP_COMMIT();
    load_tile(1, 1); CP_COMMIT();

    for (int it = 0; it < NIT; it++) {
        CP_WAIT(1);
        __syncthreads();

        uint32_t aB = sbase + (it % 3) * F2_STAGE;
        uint32_t bB = aB + 16384;

#pragma unroll
        for (int ks = 0; ks < 4; ks++) {
            uint32_t a[2][4];
#pragma unroll
            for (int mt = 0; mt < 2; mt++) {
                int row  = mw + mt * 16 + ((l >> 3) & 1) * 8 + (l & 7);
                int kbyt = ks * 32 + (l >> 4) * 16;
                ldsm_x4(aB + SWZ((uint32_t)(row * 128 + kbyt)), a[mt]);
            }
            int krow = ks * 16 + ((l >> 3) & 1) * 8 + (l & 7);
            uint32_t rb0 = krow * 128 + (nw + (l >> 4) * 8) * 2;
            uint32_t rb1 = rb0 + 32;
            uint32_t s0 = SWZ(rb0), s1 = SWZ(rb1);

            uint32_t bh[8];
            ldsm_x4_t(bB + s0, bh); ldsm_x4_t(bB + s1, bh + 4);
#pragma unroll
            for (int mt = 0; mt < 2; mt++)
#pragma unroll
                for (int nj = 0; nj < 4; nj++)
                    mma_f16(acc[mt][nj], a[mt], &bh[nj * 2]);
        }

        if (it + 2 < NIT) load_tile(it + 2, (it + 2) % 3);
        CP_COMMIT();
    }

    // ---- epilogue: out[tok] += w * acc ----
#pragma unroll
    for (int mt = 0; mt < 2; mt++) {
#pragma unroll
        for (int hf = 0; hf < 2; hf++) {
            int row = m0 + mw + mt * 16 + (l >> 2) + hf * 8;
            if (row < cnt) {
                int   tok = g_tok[e * NTOK + row];
                float w   = g_wt [e * NTOK + row];
                float* orow = out + (size_t)tok * DIM + n0 + nw;
#pragma unroll
                for (int nj = 0; nj < 4; nj++) {
                    int c = nj * 8 + (l & 3) * 2;
                    atomicAdd(&orow[c],     w * acc[mt][nj][hf * 2 + 0]);
                    atomicAdd(&orow[c + 1], w * acc[mt][nj][hf * 2 + 1]);
                }
            }
        }
    }
}

// ---------------------------------------------------------------------------
// Launch
// ---------------------------------------------------------------------------
extern "C" void kernel_launch(void* const* d_in, const int* in_sizes, int n_in,
                              void* d_out, int out_size) {
    const float* x  = (const float*)d_in[0];
    const float* Wg = (const float*)d_in[1];
    const float* W1 = (const float*)d_in[2];
    const float* W3 = (const float*)d_in[3];
    const float* W2 = (const float*)d_in[4];
    float* out = (float*)d_out;

    cudaFuncSetAttribute(ffn1_kernel,
        cudaFuncAttributeMaxDynamicSharedMemorySize, 3 * F1_STAGE);
    cudaFuncSetAttribute(ffn2_kernel,
        cudaFuncAttributeMaxDynamicSharedMemorySize, 3 * F2_STAGE);

    prep_kernel<<<3 * 1024, 512>>>((const float4*)W1, (const float4*)W3,
                                   (const float4*)W2, (float4*)out,
                                   out_size / 4);
    route_kernel<<<NTOK / 8, 256>>>((const float4*)x, Wg);

    dim3 g1(HID / 64, NTOK / 128, NE);    // 32 x 32 x 8
    ffn1_kernel<<<g1, 256, 3 * F1_STAGE>>>();

    dim3 g2(DIM / 64, NTOK / 128, NE);    // 16 x 32 x 8
    ffn2_kernel<<<g2, 256, 3 * F2_STAGE>>>(out);
}